// round 1
// baseline (speedup 1.0000x reference)
#include <cuda_runtime.h>

// ---------------- problem constants ----------------
#define cN   50000
#define cE   800000
#define cD   64
#define cHD  256
#define cB   8
#define cNPG 6250
#define LSLOPE 0.01f

// ---------------- scratch (device globals; no runtime allocation) ----------------
__device__ float g_HHbuf[cN * 768];     // [ni(256) | nj(256) | n(256)] per node
__device__ float g_a[cE * 4];           // attention logits per edge/head
__device__ float g_w1[cE * 64];         // layer-0 edge feats (head-mean), input to layer 1
__device__ float g_h1[cN * 64];
__device__ float g_h2[cN * 64];
__device__ int   g_counts[cN];
__device__ int   g_rowptr[cN + 1];
__device__ int   g_cursor[cN];
__device__ int   g_csr[cE];
__device__ int   g_bsum[128];
__device__ float g_pooled[cB * 192];

// ---------------- helpers ----------------
__device__ __forceinline__ float2 ffma2(float2 a, float2 b, float2 c) {
    union U { float2 f; unsigned long long u; };
    U ua, ub, uc, ud;
    ua.f = a; ub.f = b; uc.f = c;
    asm("fma.rn.f32x2 %0, %1, %2, %3;" : "=l"(ud.u) : "l"(ua.u), "l"(ub.u), "l"(uc.u));
    return ud.f;
}
__device__ __forceinline__ float4 add4(float4 a, float4 b) {
    return make_float4(a.x + b.x, a.y + b.y, a.z + b.z, a.w + b.w);
}
__device__ __forceinline__ float4 sub4(float4 a, float4 b) {
    return make_float4(a.x - b.x, a.y - b.y, a.z - b.z, a.w - b.w);
}
__device__ __forceinline__ float4 max4(float4 a, float4 b) {
    return make_float4(fmaxf(a.x, b.x), fmaxf(a.y, b.y), fmaxf(a.z, b.z), fmaxf(a.w, b.w));
}
__device__ __forceinline__ float4 exp4(float4 a) {
    return make_float4(__expf(a.x), __expf(a.y), __expf(a.z), __expf(a.w));
}
__device__ __forceinline__ float4 lrelu4(float4 x) {
    x.x = x.x > 0.f ? x.x : LSLOPE * x.x;
    x.y = x.y > 0.f ? x.y : LSLOPE * x.y;
    x.z = x.z > 0.f ? x.z : LSLOPE * x.z;
    x.w = x.w > 0.f ? x.w : LSLOPE * x.w;
    return x;
}
__device__ __forceinline__ float4 shflxor4(float4 v, int m) {
    v.x = __shfl_xor_sync(0xffffffffu, v.x, m);
    v.y = __shfl_xor_sync(0xffffffffu, v.y, m);
    v.z = __shfl_xor_sync(0xffffffffu, v.z, m);
    v.w = __shfl_xor_sync(0xffffffffu, v.w, m);
    return v;
}

// ---------------- CSR build ----------------
__global__ void zero_k() {
    int i = blockIdx.x * 256 + threadIdx.x;
    if (i < cN) g_counts[i] = 0;
    if (i < cB * 192) g_pooled[i] = 0.f;
}
__global__ void hist_k(const int* __restrict__ dst) {
    int i = blockIdx.x * 256 + threadIdx.x;
    if (i < cE) atomicAdd(&g_counts[dst[i]], 1);
}
__global__ void scan1_k() {
    __shared__ int sh[512];
    int tid = threadIdx.x;
    int idx = blockIdx.x * 512 + tid;
    int v = (idx < cN) ? g_counts[idx] : 0;
    sh[tid] = v;
    __syncthreads();
    for (int off = 1; off < 512; off <<= 1) {
        int t = (tid >= off) ? sh[tid - off] : 0;
        __syncthreads();
        sh[tid] += t;
        __syncthreads();
    }
    if (idx < cN) g_rowptr[idx] = sh[tid] - v;   // exclusive within block
    if (tid == 511) g_bsum[blockIdx.x] = sh[511];
}
__global__ void scan2_k() {
    if (threadIdx.x == 0) {
        int run = 0;
        for (int i = 0; i < 98; i++) { int t = g_bsum[i]; g_bsum[i] = run; run += t; }
    }
}
__global__ void scan3_k() {
    int idx = blockIdx.x * 256 + threadIdx.x;
    if (idx < cN) {
        int v = g_rowptr[idx] + g_bsum[idx >> 9];
        g_rowptr[idx] = v;
        g_cursor[idx] = v;
    }
    if (idx == 0) g_rowptr[cN] = cE;
}
__global__ void scat_k(const int* __restrict__ dst) {
    int i = blockIdx.x * 256 + threadIdx.x;
    if (i < cE) {
        int pos = atomicAdd(&g_cursor[dst[i]], 1);
        g_csr[pos] = i;
    }
}

// ---------------- node GEMM: (M,64) @ (64,256) -> g_HHbuf cols [co..co+256) ----------------
// lane owns output float4 slots l and l+32 (cols 4l..4l+3 and 128+4l..128+4l+3)
__global__ void __launch_bounds__(256) node_gemm_k(const float* __restrict__ Aext,
                                                  const float* __restrict__ W,
                                                  int M, int co4) {
    extern __shared__ float sm[];
    float4* Ws4 = (float4*)sm;                 // 4096 float4 = 64KB
    float2* As2 = (float2*)(sm + 16384);       // 4096 float2 = 32KB (duplicated A)
    const float* A = Aext ? Aext : g_h1;
    int tid = threadIdx.x;
    const float4* Wg = (const float4*)W;
#pragma unroll 4
    for (int i = tid; i < 4096; i += 256) Ws4[i] = Wg[i];
    int row0 = blockIdx.x * 64;
    for (int i = tid; i < 4096; i += 256) {
        int r = i >> 6, k = i & 63;
        int gr = row0 + r;
        float v = (gr < M) ? A[gr * 64 + k] : 0.f;
        As2[i] = make_float2(v, v);
    }
    __syncthreads();
    int lane = tid & 31, warp = tid >> 5;
    float2 aA0[8], aA1[8], aB0[8], aB1[8];
#pragma unroll
    for (int t = 0; t < 8; t++) {
        aA0[t] = make_float2(0.f, 0.f); aA1[t] = make_float2(0.f, 0.f);
        aB0[t] = make_float2(0.f, 0.f); aB1[t] = make_float2(0.f, 0.f);
    }
#pragma unroll 2
    for (int k = 0; k < 64; k++) {
        float4 bA = Ws4[k * 64 + lane];
        float4 bB = Ws4[k * 64 + 32 + lane];
        float2 bA0 = make_float2(bA.x, bA.y), bA1 = make_float2(bA.z, bA.w);
        float2 bB0 = make_float2(bB.x, bB.y), bB1 = make_float2(bB.z, bB.w);
#pragma unroll
        for (int t = 0; t < 8; t++) {
            float2 aa = As2[(warp * 8 + t) * 64 + k];
            aA0[t] = ffma2(aa, bA0, aA0[t]);
            aA1[t] = ffma2(aa, bA1, aA1[t]);
            aB0[t] = ffma2(aa, bB0, aB0[t]);
            aB1[t] = ffma2(aa, bB1, aB1[t]);
        }
    }
#pragma unroll
    for (int t = 0; t < 8; t++) {
        int r = row0 + warp * 8 + t;
        if (r < M) {
            float4* o = (float4*)(g_HHbuf + (size_t)r * 768);
            o[co4 + lane]      = make_float4(aA0[t].x, aA0[t].y, aA1[t].x, aA1[t].y);
            o[co4 + 32 + lane] = make_float4(aB0[t].x, aB0[t].y, aB1[t].x, aB1[t].y);
        }
    }
}

// ---------------- fused edge kernel ----------------
// per edge: f = w@Wf + Hni[src] + Hnj[dst] + bias ; e = leaky(f)
// a[e,h] = <e[h,:], attn[h,:]> ; (layer0) w1[e,:] = mean_h e[h,:]
__global__ void __launch_bounds__(256) edge_k(const float* __restrict__ Afext,
                                              const int* __restrict__ src,
                                              const int* __restrict__ dst,
                                              const float* __restrict__ Wf,
                                              const float* __restrict__ attn,
                                              const float* __restrict__ bias,
                                              int write_wnext) {
    extern __shared__ float sm[];
    float4* Ws4 = (float4*)sm;                     // 64KB
    float2* As2 = (float2*)(sm + 16384);           // 32KB
    float*  bias_s = sm + 16384 + 8192;            // 256
    float*  attn_s = bias_s + 256;                 // 256
    const float* Af = Afext ? Afext : g_w1;
    int tid = threadIdx.x;
    const float4* Wg = (const float4*)Wf;
#pragma unroll 4
    for (int i = tid; i < 4096; i += 256) Ws4[i] = Wg[i];
    int e0 = blockIdx.x * 64;
    for (int i = tid; i < 4096; i += 256) {
        int el = i >> 6, k = i & 63;
        float v = Af[(size_t)(e0 + el) * 64 + k];
        As2[i] = make_float2(v, v);
    }
    bias_s[tid] = bias[tid];
    attn_s[tid] = attn[tid];
    __syncthreads();
    int lane = tid & 31, warp = tid >> 5;
    float2 aA0[8], aA1[8], aB0[8], aB1[8];
#pragma unroll
    for (int t = 0; t < 8; t++) {
        aA0[t] = make_float2(0.f, 0.f); aA1[t] = make_float2(0.f, 0.f);
        aB0[t] = make_float2(0.f, 0.f); aB1[t] = make_float2(0.f, 0.f);
    }
#pragma unroll 2
    for (int k = 0; k < 64; k++) {
        float4 bA = Ws4[k * 64 + lane];
        float4 bB = Ws4[k * 64 + 32 + lane];
        float2 bA0 = make_float2(bA.x, bA.y), bA1 = make_float2(bA.z, bA.w);
        float2 bB0 = make_float2(bB.x, bB.y), bB1 = make_float2(bB.z, bB.w);
#pragma unroll
        for (int t = 0; t < 8; t++) {
            float2 aa = As2[(warp * 8 + t) * 64 + k];
            aA0[t] = ffma2(aa, bA0, aA0[t]);
            aA1[t] = ffma2(aa, bA1, aA1[t]);
            aB0[t] = ffma2(aa, bB0, aB0[t]);
            aB1[t] = ffma2(aa, bB1, aB1[t]);
        }
    }
    const float4* bias4 = (const float4*)bias_s;
    const float4* attn4 = (const float4*)attn_s;
    float4 biA = bias4[lane], biB = bias4[32 + lane];
    float4 atA = attn4[lane], atB = attn4[32 + lane];
#pragma unroll
    for (int t = 0; t < 8; t++) {
        int e = e0 + warp * 8 + t;
        int s = src[e], d = dst[e];
        const float4* hs4 = (const float4*)(g_HHbuf + (size_t)s * 768);
        const float4* hd4 = (const float4*)(g_HHbuf + (size_t)d * 768);
        float4 fA = make_float4(aA0[t].x, aA0[t].y, aA1[t].x, aA1[t].y);
        float4 fB = make_float4(aB0[t].x, aB0[t].y, aB1[t].x, aB1[t].y);
        fA = add4(add4(fA, hs4[lane]),      add4(hd4[64 + lane], biA));
        fB = add4(add4(fB, hs4[32 + lane]), add4(hd4[96 + lane], biB));
        fA = lrelu4(fA);
        fB = lrelu4(fB);
        // attention dot, reduce over 16-lane halves (heads stay separated)
        float pa = fA.x * atA.x + fA.y * atA.y + fA.z * atA.z + fA.w * atA.w;
        float pb = fB.x * atB.x + fB.y * atB.y + fB.z * atB.z + fB.w * atB.w;
#pragma unroll
        for (int off = 8; off >= 1; off >>= 1) {
            pa += __shfl_down_sync(0xffffffffu, pa, off);
            pb += __shfl_down_sync(0xffffffffu, pb, off);
        }
        if (lane == 0)  { g_a[e * 4 + 0] = pa; g_a[e * 4 + 2] = pb; }
        if (lane == 16) { g_a[e * 4 + 1] = pa; g_a[e * 4 + 3] = pb; }
        if (write_wnext) {
            float4 s4 = add4(fA, fB);       // heads {h, 2+h} of this lane
            s4.x += __shfl_down_sync(0xffffffffu, s4.x, 16);
            s4.y += __shfl_down_sync(0xffffffffu, s4.y, 16);
            s4.z += __shfl_down_sync(0xffffffffu, s4.z, 16);
            s4.w += __shfl_down_sync(0xffffffffu, s4.w, 16);
            if (lane < 16) {
                ((float4*)(g_w1 + (size_t)e * 64))[lane] =
                    make_float4(s4.x * 0.25f, s4.y * 0.25f, s4.z * 0.25f, s4.w * 0.25f);
            }
        }
    }
}

// ---------------- softmax + aggregation (warp per dst node, CSR) ----------------
__global__ void __launch_bounds__(256) agg_k(const int* __restrict__ src, int layer) {
    int lane = threadIdx.x & 31, warp = threadIdx.x >> 5;
    int node = blockIdx.x * 8 + warp;
    float* hout = layer ? g_h2 : g_h1;
    float4* out4 = (float4*)(hout + (size_t)node * 64);
    int base = g_rowptr[node];
    int deg  = g_rowptr[node + 1] - base;
    if (deg == 0) {
        if (lane < 16) out4[lane] = make_float4(0.f, 0.f, 0.f, 0.f);
        return;
    }
    const float4* a4 = (const float4*)g_a;
    float4 m = make_float4(-3.0e38f, -3.0e38f, -3.0e38f, -3.0e38f);
    for (int j = lane; j < deg; j += 32) m = max4(m, a4[g_csr[base + j]]);
#pragma unroll
    for (int off = 16; off >= 1; off >>= 1) m = max4(m, shflxor4(m, off));
    float4 ss = make_float4(0.f, 0.f, 0.f, 0.f);
    for (int j = lane; j < deg; j += 32) ss = add4(ss, exp4(sub4(a4[g_csr[base + j]], m)));
#pragma unroll
    for (int off = 16; off >= 1; off >>= 1) ss = add4(ss, shflxor4(ss, off));
    float4 inv = make_float4(1.f / ss.x, 1.f / ss.y, 1.f / ss.z, 1.f / ss.w);

    float4 accA = make_float4(0.f, 0.f, 0.f, 0.f);
    float4 accB = make_float4(0.f, 0.f, 0.f, 0.f);
    int ej = g_csr[base];
    for (int j = 0; j < deg; j++) {
        int en = (j + 1 < deg) ? g_csr[base + j + 1] : 0;
        int s = src[ej];
        float4 av = a4[ej];
        float4 wv = exp4(sub4(av, m));
        wv.x *= inv.x; wv.y *= inv.y; wv.z *= inv.z; wv.w *= inv.w;
        float wA = (lane < 16) ? wv.x : wv.y;   // heads 0/1
        float wB = (lane < 16) ? wv.z : wv.w;   // heads 2/3
        const float4* hn = (const float4*)(g_HHbuf + (size_t)s * 768);
        float4 vA = hn[128 + lane], vB = hn[160 + lane];
        accA.x = fmaf(wA, vA.x, accA.x); accA.y = fmaf(wA, vA.y, accA.y);
        accA.z = fmaf(wA, vA.z, accA.z); accA.w = fmaf(wA, vA.w, accA.w);
        accB.x = fmaf(wB, vB.x, accB.x); accB.y = fmaf(wB, vB.y, accB.y);
        accB.z = fmaf(wB, vB.z, accB.z); accB.w = fmaf(wB, vB.w, accB.w);
        ej = en;
    }
    float4 t4 = add4(accA, accB);              // heads {h, 2+h}
    t4.x += __shfl_down_sync(0xffffffffu, t4.x, 16);
    t4.y += __shfl_down_sync(0xffffffffu, t4.y, 16);
    t4.z += __shfl_down_sync(0xffffffffu, t4.z, 16);
    t4.w += __shfl_down_sync(0xffffffffu, t4.w, 16);
    if (lane < 16)
        out4[lane] = make_float4(t4.x * 0.25f, t4.y * 0.25f, t4.z * 0.25f, t4.w * 0.25f);
}

// ---------------- pooling + classifier ----------------
__global__ void pool_k(const float* __restrict__ feat) {
    int g = blockIdx.x >> 5, sub = blockIdx.x & 31;
    int n0 = sub * 196;
    int n1 = n0 + 196; if (n1 > cNPG) n1 = cNPG;
    int t = threadIdx.x;  // 0..191
    float sum = 0.f;
    for (int n = n0; n < n1; n++) {
        int gn = g * cNPG + n;
        float v;
        if (t < 64)       v = feat[(size_t)gn * 64 + t];
        else if (t < 128) v = g_h1[(size_t)gn * 64 + (t - 64)];
        else              v = g_h2[(size_t)gn * 64 + (t - 128)];
        sum += v;
    }
    atomicAdd(&g_pooled[g * 192 + t], sum);
}
__global__ void final_k(const float* __restrict__ Wlin, const float* __restrict__ blin,
                        float* __restrict__ out) {
    int t = threadIdx.x;
    if (t < 16) {
        int b = t >> 1, c = t & 1;
        float acc = blin[c];
        const float invn = 1.0f / (float)cNPG;
        for (int k = 0; k < 192; k++)
            acc += (g_pooled[b * 192 + k] * invn) * Wlin[k * 2 + c];
        out[t] = acc;
    }
}

// ---------------- launch ----------------
extern "C" void kernel_launch(void* const* d_in, const int* in_sizes, int n_in,
                              void* d_out, int out_size) {
    const float* feat   = (const float*)d_in[0];
    const float* ew     = (const float*)d_in[1];
    const int*   src    = (const int*)d_in[2];
    const int*   dst    = (const int*)d_in[3];
    const float* W_node = (const float*)d_in[4];
    const float* W_ni   = (const float*)d_in[5];
    const float* W_nj   = (const float*)d_in[6];
    const float* W_fij  = (const float*)d_in[7];
    const float* attn   = (const float*)d_in[8];
    const float* bias_e = (const float*)d_in[9];
    const float* W_lin  = (const float*)d_in[10];
    const float* b_lin  = (const float*)d_in[11];
    float* out = (float*)d_out;

    const int SMEM_GEMM = (16384 + 8192) * 4;        // 98304
    const int SMEM_EDGE = (16384 + 8192 + 512) * 4;  // 100352
    cudaFuncSetAttribute((const void*)node_gemm_k,
                         cudaFuncAttributeMaxDynamicSharedMemorySize, SMEM_GEMM);
    cudaFuncSetAttribute((const void*)edge_k,
                         cudaFuncAttributeMaxDynamicSharedMemorySize, SMEM_EDGE);

    // CSR build + zero accumulators
    zero_k<<<(cN + 255) / 256, 256>>>();
    hist_k<<<(cE + 255) / 256, 256>>>(dst);
    scan1_k<<<98, 512>>>();
    scan2_k<<<1, 32>>>();
    scan3_k<<<(cN + 255) / 256, 256>>>();
    scat_k<<<(cE + 255) / 256, 256>>>(dst);

    const int GB = (cN + 63) / 64;  // 782 node-gemm blocks

    // ---- layer 0 (h = feat, w = eweight) ----
    node_gemm_k<<<GB, 256, SMEM_GEMM>>>(feat, W_ni,   cN, 0);
    node_gemm_k<<<GB, 256, SMEM_GEMM>>>(feat, W_nj,   cN, 64);
    node_gemm_k<<<GB, 256, SMEM_GEMM>>>(feat, W_node, cN, 128);
    edge_k<<<cE / 64, 256, SMEM_EDGE>>>(ew, src, dst, W_fij, attn, bias_e, 1);
    agg_k<<<cN / 8, 256>>>(src, 0);

    // ---- layer 1 (h = g_h1, w = g_w1) ----
    node_gemm_k<<<GB, 256, SMEM_GEMM>>>(nullptr, W_ni + 16384,   cN, 0);
    node_gemm_k<<<GB, 256, SMEM_GEMM>>>(nullptr, W_nj + 16384,   cN, 64);
    node_gemm_k<<<GB, 256, SMEM_GEMM>>>(nullptr, W_node + 16384, cN, 128);
    edge_k<<<cE / 64, 256, SMEM_EDGE>>>(nullptr, src, dst, W_fij + 16384,
                                        attn + 256, bias_e + 256, 0);
    agg_k<<<cN / 8, 256>>>(src, 1);

    // ---- JK concat pooling + linear ----
    pool_k<<<cB * 32, 192>>>(feat);
    final_k<<<1, 32>>>(W_lin, b_lin, out);
}

// round 2
// speedup vs baseline: 1.0018x; 1.0018x over previous
#include <cuda_runtime.h>

// ---------------- problem constants ----------------
#define cN   50000
#define cE   800000
#define cD   64
#define cHD  256
#define cB   8
#define cNPG 6250
#define LSLOPE 0.01f

// ---------------- scratch (device globals; no runtime allocation) ----------------
__device__ float g_HHbuf[cN * 768];     // [ni(256) | nj(256) | n(256)] per node
__device__ float g_a[cE * 4];           // attention logits per edge/head
__device__ float g_w1[cE * 64];         // layer-0 edge feats (head-mean), input to layer 1
__device__ float g_h1[cN * 64];
__device__ float g_h2[cN * 64];
__device__ int   g_counts[cN];
__device__ int   g_rowptr[cN + 1];
__device__ int   g_cursor[cN];
__device__ int   g_csr[cE];
__device__ int   g_bsum[128];
__device__ float g_pooled[cB * 192];

// ---------------- helpers ----------------
__device__ __forceinline__ float2 ffma2(float2 a, float2 b, float2 c) {
    union U { float2 f; unsigned long long u; };
    U ua, ub, uc, ud;
    ua.f = a; ub.f = b; uc.f = c;
    asm("fma.rn.f32x2 %0, %1, %2, %3;" : "=l"(ud.u) : "l"(ua.u), "l"(ub.u), "l"(uc.u));
    return ud.f;
}
__device__ __forceinline__ float4 add4(float4 a, float4 b) {
    return make_float4(a.x + b.x, a.y + b.y, a.z + b.z, a.w + b.w);
}
__device__ __forceinline__ float4 sub4(float4 a, float4 b) {
    return make_float4(a.x - b.x, a.y - b.y, a.z - b.z, a.w - b.w);
}
__device__ __forceinline__ float4 max4(float4 a, float4 b) {
    return make_float4(fmaxf(a.x, b.x), fmaxf(a.y, b.y), fmaxf(a.z, b.z), fmaxf(a.w, b.w));
}
__device__ __forceinline__ float4 exp4(float4 a) {
    return make_float4(__expf(a.x), __expf(a.y), __expf(a.z), __expf(a.w));
}
__device__ __forceinline__ float4 lrelu4(float4 x) {
    x.x = x.x > 0.f ? x.x : LSLOPE * x.x;
    x.y = x.y > 0.f ? x.y : LSLOPE * x.y;
    x.z = x.z > 0.f ? x.z : LSLOPE * x.z;
    x.w = x.w > 0.f ? x.w : LSLOPE * x.w;
    return x;
}
__device__ __forceinline__ float4 shflxor4(float4 v, int m) {
    v.x = __shfl_xor_sync(0xffffffffu, v.x, m);
    v.y = __shfl_xor_sync(0xffffffffu, v.y, m);
    v.z = __shfl_xor_sync(0xffffffffu, v.z, m);
    v.w = __shfl_xor_sync(0xffffffffu, v.w, m);
    return v;
}

// ---------------- CSR build ----------------
__global__ void zero_k() {
    int i = blockIdx.x * 256 + threadIdx.x;
    if (i < cN) g_counts[i] = 0;
    if (i < cB * 192) g_pooled[i] = 0.f;
}
__global__ void hist_k(const int* __restrict__ dst) {
    int i = blockIdx.x * 256 + threadIdx.x;
    if (i < cE) atomicAdd(&g_counts[dst[i]], 1);
}
__global__ void scan1_k() {
    __shared__ int sh[512];
    int tid = threadIdx.x;
    int idx = blockIdx.x * 512 + tid;
    int v = (idx < cN) ? g_counts[idx] : 0;
    sh[tid] = v;
    __syncthreads();
    for (int off = 1; off < 512; off <<= 1) {
        int t = (tid >= off) ? sh[tid - off] : 0;
        __syncthreads();
        sh[tid] += t;
        __syncthreads();
    }
    if (idx < cN) g_rowptr[idx] = sh[tid] - v;   // exclusive within block
    if (tid == 511) g_bsum[blockIdx.x] = sh[511];
}
__global__ void scan2_k() {
    if (threadIdx.x == 0) {
        int run = 0;
        for (int i = 0; i < 98; i++) { int t = g_bsum[i]; g_bsum[i] = run; run += t; }
    }
}
__global__ void scan3_k() {
    int idx = blockIdx.x * 256 + threadIdx.x;
    if (idx < cN) {
        int v = g_rowptr[idx] + g_bsum[idx >> 9];
        g_rowptr[idx] = v;
        g_cursor[idx] = v;
    }
    if (idx == 0) g_rowptr[cN] = cE;
}
__global__ void scat_k(const int* __restrict__ dst) {
    int i = blockIdx.x * 256 + threadIdx.x;
    if (i < cE) {
        int pos = atomicAdd(&g_cursor[dst[i]], 1);
        g_csr[pos] = i;
    }
}

// ---------------- node GEMM: (M,64) @ (64,256) -> g_HHbuf cols [co..co+256) ----------------
// lane owns output float4 slots l and l+32 (cols 4l..4l+3 and 128+4l..128+4l+3)
__global__ void __launch_bounds__(256) node_gemm_k(const float* __restrict__ Aext,
                                                  const float* __restrict__ W,
                                                  int M, int co4) {
    extern __shared__ float sm[];
    float4* Ws4 = (float4*)sm;                 // 4096 float4 = 64KB
    float2* As2 = (float2*)(sm + 16384);       // 4096 float2 = 32KB (duplicated A)
    const float* A = Aext ? Aext : g_h1;
    int tid = threadIdx.x;
    const float4* Wg = (const float4*)W;
#pragma unroll 4
    for (int i = tid; i < 4096; i += 256) Ws4[i] = Wg[i];
    int row0 = blockIdx.x * 64;
    for (int i = tid; i < 4096; i += 256) {
        int r = i >> 6, k = i & 63;
        int gr = row0 + r;
        float v = (gr < M) ? A[gr * 64 + k] : 0.f;
        As2[i] = make_float2(v, v);
    }
    __syncthreads();
    int lane = tid & 31, warp = tid >> 5;
    float2 aA0[8], aA1[8], aB0[8], aB1[8];
#pragma unroll
    for (int t = 0; t < 8; t++) {
        aA0[t] = make_float2(0.f, 0.f); aA1[t] = make_float2(0.f, 0.f);
        aB0[t] = make_float2(0.f, 0.f); aB1[t] = make_float2(0.f, 0.f);
    }
#pragma unroll 2
    for (int k = 0; k < 64; k++) {
        float4 bA = Ws4[k * 64 + lane];
        float4 bB = Ws4[k * 64 + 32 + lane];
        float2 bA0 = make_float2(bA.x, bA.y), bA1 = make_float2(bA.z, bA.w);
        float2 bB0 = make_float2(bB.x, bB.y), bB1 = make_float2(bB.z, bB.w);
#pragma unroll
        for (int t = 0; t < 8; t++) {
            float2 aa = As2[(warp * 8 + t) * 64 + k];
            aA0[t] = ffma2(aa, bA0, aA0[t]);
            aA1[t] = ffma2(aa, bA1, aA1[t]);
            aB0[t] = ffma2(aa, bB0, aB0[t]);
            aB1[t] = ffma2(aa, bB1, aB1[t]);
        }
    }
#pragma unroll
    for (int t = 0; t < 8; t++) {
        int r = row0 + warp * 8 + t;
        if (r < M) {
            float4* o = (float4*)(g_HHbuf + (size_t)r * 768);
            o[co4 + lane]      = make_float4(aA0[t].x, aA0[t].y, aA1[t].x, aA1[t].y);
            o[co4 + 32 + lane] = make_float4(aB0[t].x, aB0[t].y, aB1[t].x, aB1[t].y);
        }
    }
}

// ---------------- fused edge kernel ----------------
// per edge: f = w@Wf + Hni[src] + Hnj[dst] + bias ; e = leaky(f)
// a[e,h] = <e[h,:], attn[h,:]> ; (layer0) w1[e,:] = mean_h e[h,:]
__global__ void __launch_bounds__(256) edge_k(const float* __restrict__ Afext,
                                              const int* __restrict__ src,
                                              const int* __restrict__ dst,
                                              const float* __restrict__ Wf,
                                              const float* __restrict__ attn,
                                              const float* __restrict__ bias,
                                              int write_wnext) {
    extern __shared__ float sm[];
    float4* Ws4 = (float4*)sm;                     // 64KB
    float2* As2 = (float2*)(sm + 16384);           // 32KB
    float*  bias_s = sm + 16384 + 8192;            // 256
    float*  attn_s = bias_s + 256;                 // 256
    const float* Af = Afext ? Afext : g_w1;
    int tid = threadIdx.x;
    const float4* Wg = (const float4*)Wf;
#pragma unroll 4
    for (int i = tid; i < 4096; i += 256) Ws4[i] = Wg[i];
    int e0 = blockIdx.x * 64;
    for (int i = tid; i < 4096; i += 256) {
        int el = i >> 6, k = i & 63;
        float v = Af[(size_t)(e0 + el) * 64 + k];
        As2[i] = make_float2(v, v);
    }
    bias_s[tid] = bias[tid];
    attn_s[tid] = attn[tid];
    __syncthreads();
    int lane = tid & 31, warp = tid >> 5;
    float2 aA0[8], aA1[8], aB0[8], aB1[8];
#pragma unroll
    for (int t = 0; t < 8; t++) {
        aA0[t] = make_float2(0.f, 0.f); aA1[t] = make_float2(0.f, 0.f);
        aB0[t] = make_float2(0.f, 0.f); aB1[t] = make_float2(0.f, 0.f);
    }
#pragma unroll 2
    for (int k = 0; k < 64; k++) {
        float4 bA = Ws4[k * 64 + lane];
        float4 bB = Ws4[k * 64 + 32 + lane];
        float2 bA0 = make_float2(bA.x, bA.y), bA1 = make_float2(bA.z, bA.w);
        float2 bB0 = make_float2(bB.x, bB.y), bB1 = make_float2(bB.z, bB.w);
#pragma unroll
        for (int t = 0; t < 8; t++) {
            float2 aa = As2[(warp * 8 + t) * 64 + k];
            aA0[t] = ffma2(aa, bA0, aA0[t]);
            aA1[t] = ffma2(aa, bA1, aA1[t]);
            aB0[t] = ffma2(aa, bB0, aB0[t]);
            aB1[t] = ffma2(aa, bB1, aB1[t]);
        }
    }
    const float4* bias4 = (const float4*)bias_s;
    const float4* attn4 = (const float4*)attn_s;
    float4 biA = bias4[lane], biB = bias4[32 + lane];
    float4 atA = attn4[lane], atB = attn4[32 + lane];
#pragma unroll
    for (int t = 0; t < 8; t++) {
        int e = e0 + warp * 8 + t;
        int s = src[e], d = dst[e];
        const float4* hs4 = (const float4*)(g_HHbuf + (size_t)s * 768);
        const float4* hd4 = (const float4*)(g_HHbuf + (size_t)d * 768);
        float4 fA = make_float4(aA0[t].x, aA0[t].y, aA1[t].x, aA1[t].y);
        float4 fB = make_float4(aB0[t].x, aB0[t].y, aB1[t].x, aB1[t].y);
        fA = add4(add4(fA, hs4[lane]),      add4(hd4[64 + lane], biA));
        fB = add4(add4(fB, hs4[32 + lane]), add4(hd4[96 + lane], biB));
        fA = lrelu4(fA);
        fB = lrelu4(fB);
        // attention dot, reduce over 16-lane halves (heads stay separated)
        float pa = fA.x * atA.x + fA.y * atA.y + fA.z * atA.z + fA.w * atA.w;
        float pb = fB.x * atB.x + fB.y * atB.y + fB.z * atB.z + fB.w * atB.w;
#pragma unroll
        for (int off = 8; off >= 1; off >>= 1) {
            pa += __shfl_down_sync(0xffffffffu, pa, off);
            pb += __shfl_down_sync(0xffffffffu, pb, off);
        }
        if (lane == 0)  { g_a[e * 4 + 0] = pa; g_a[e * 4 + 2] = pb; }
        if (lane == 16) { g_a[e * 4 + 1] = pa; g_a[e * 4 + 3] = pb; }
        if (write_wnext) {
            float4 s4 = add4(fA, fB);       // heads {h, 2+h} of this lane
            s4.x += __shfl_down_sync(0xffffffffu, s4.x, 16);
            s4.y += __shfl_down_sync(0xffffffffu, s4.y, 16);
            s4.z += __shfl_down_sync(0xffffffffu, s4.z, 16);
            s4.w += __shfl_down_sync(0xffffffffu, s4.w, 16);
            if (lane < 16) {
                ((float4*)(g_w1 + (size_t)e * 64))[lane] =
                    make_float4(s4.x * 0.25f, s4.y * 0.25f, s4.z * 0.25f, s4.w * 0.25f);
            }
        }
    }
}

// ---------------- softmax + aggregation (warp per dst node, CSR) ----------------
__global__ void __launch_bounds__(256) agg_k(const int* __restrict__ src, int layer) {
    int lane = threadIdx.x & 31, warp = threadIdx.x >> 5;
    int node = blockIdx.x * 8 + warp;
    float* hout = layer ? g_h2 : g_h1;
    float4* out4 = (float4*)(hout + (size_t)node * 64);
    int base = g_rowptr[node];
    int deg  = g_rowptr[node + 1] - base;
    if (deg == 0) {
        if (lane < 16) out4[lane] = make_float4(0.f, 0.f, 0.f, 0.f);
        return;
    }
    const float4* a4 = (const float4*)g_a;
    float4 m = make_float4(-3.0e38f, -3.0e38f, -3.0e38f, -3.0e38f);
    for (int j = lane; j < deg; j += 32) m = max4(m, a4[g_csr[base + j]]);
#pragma unroll
    for (int off = 16; off >= 1; off >>= 1) m = max4(m, shflxor4(m, off));
    float4 ss = make_float4(0.f, 0.f, 0.f, 0.f);
    for (int j = lane; j < deg; j += 32) ss = add4(ss, exp4(sub4(a4[g_csr[base + j]], m)));
#pragma unroll
    for (int off = 16; off >= 1; off >>= 1) ss = add4(ss, shflxor4(ss, off));
    float4 inv = make_float4(1.f / ss.x, 1.f / ss.y, 1.f / ss.z, 1.f / ss.w);

    float4 accA = make_float4(0.f, 0.f, 0.f, 0.f);
    float4 accB = make_float4(0.f, 0.f, 0.f, 0.f);
    int ej = g_csr[base];
    for (int j = 0; j < deg; j++) {
        int en = (j + 1 < deg) ? g_csr[base + j + 1] : 0;
        int s = src[ej];
        float4 av = a4[ej];
        float4 wv = exp4(sub4(av, m));
        wv.x *= inv.x; wv.y *= inv.y; wv.z *= inv.z; wv.w *= inv.w;
        float wA = (lane < 16) ? wv.x : wv.y;   // heads 0/1
        float wB = (lane < 16) ? wv.z : wv.w;   // heads 2/3
        const float4* hn = (const float4*)(g_HHbuf + (size_t)s * 768);
        float4 vA = hn[128 + lane], vB = hn[160 + lane];
        accA.x = fmaf(wA, vA.x, accA.x); accA.y = fmaf(wA, vA.y, accA.y);
        accA.z = fmaf(wA, vA.z, accA.z); accA.w = fmaf(wA, vA.w, accA.w);
        accB.x = fmaf(wB, vB.x, accB.x); accB.y = fmaf(wB, vB.y, accB.y);
        accB.z = fmaf(wB, vB.z, accB.z); accB.w = fmaf(wB, vB.w, accB.w);
        ej = en;
    }
    float4 t4 = add4(accA, accB);              // heads {h, 2+h}
    t4.x += __shfl_down_sync(0xffffffffu, t4.x, 16);
    t4.y += __shfl_down_sync(0xffffffffu, t4.y, 16);
    t4.z += __shfl_down_sync(0xffffffffu, t4.z, 16);
    t4.w += __shfl_down_sync(0xffffffffu, t4.w, 16);
    if (lane < 16)
        out4[lane] = make_float4(t4.x * 0.25f, t4.y * 0.25f, t4.z * 0.25f, t4.w * 0.25f);
}

// ---------------- pooling + classifier ----------------
__global__ void pool_k(const float* __restrict__ feat) {
    int g = blockIdx.x >> 5, sub = blockIdx.x & 31;
    int n0 = sub * 196;
    int n1 = n0 + 196; if (n1 > cNPG) n1 = cNPG;
    int t = threadIdx.x;  // 0..191
    float sum = 0.f;
    for (int n = n0; n < n1; n++) {
        int gn = g * cNPG + n;
        float v;
        if (t < 64)       v = feat[(size_t)gn * 64 + t];
        else if (t < 128) v = g_h1[(size_t)gn * 64 + (t - 64)];
        else              v = g_h2[(size_t)gn * 64 + (t - 128)];
        sum += v;
    }
    atomicAdd(&g_pooled[g * 192 + t], sum);
}
__global__ void final_k(const float* __restrict__ Wlin, const float* __restrict__ blin,
                        float* __restrict__ out) {
    int t = threadIdx.x;
    if (t < 16) {
        int b = t >> 1, c = t & 1;
        float acc = blin[c];
        const float invn = 1.0f / (float)cNPG;
        for (int k = 0; k < 192; k++)
            acc += (g_pooled[b * 192 + k] * invn) * Wlin[k * 2 + c];
        out[t] = acc;
    }
}

// ---------------- launch ----------------
extern "C" void kernel_launch(void* const* d_in, const int* in_sizes, int n_in,
                              void* d_out, int out_size) {
    const float* feat   = (const float*)d_in[0];
    const float* ew     = (const float*)d_in[1];
    const int*   src    = (const int*)d_in[2];
    const int*   dst    = (const int*)d_in[3];
    const float* W_node = (const float*)d_in[4];
    const float* W_ni   = (const float*)d_in[5];
    const float* W_nj   = (const float*)d_in[6];
    const float* W_fij  = (const float*)d_in[7];
    const float* attn   = (const float*)d_in[8];
    const float* bias_e = (const float*)d_in[9];
    const float* W_lin  = (const float*)d_in[10];
    const float* b_lin  = (const float*)d_in[11];
    float* out = (float*)d_out;

    const int SMEM_GEMM = (16384 + 8192) * 4;        // 98304
    const int SMEM_EDGE = (16384 + 8192 + 512) * 4;  // 100352
    cudaFuncSetAttribute((const void*)node_gemm_k,
                         cudaFuncAttributeMaxDynamicSharedMemorySize, SMEM_GEMM);
    cudaFuncSetAttribute((const void*)edge_k,
                         cudaFuncAttributeMaxDynamicSharedMemorySize, SMEM_EDGE);

    // CSR build + zero accumulators
    zero_k<<<(cN + 255) / 256, 256>>>();
    hist_k<<<(cE + 255) / 256, 256>>>(dst);
    scan1_k<<<98, 512>>>();
    scan2_k<<<1, 32>>>();
    scan3_k<<<(cN + 255) / 256, 256>>>();
    scat_k<<<(cE + 255) / 256, 256>>>(dst);

    const int GB = (cN + 63) / 64;  // 782 node-gemm blocks

    // ---- layer 0 (h = feat, w = eweight) ----
    node_gemm_k<<<GB, 256, SMEM_GEMM>>>(feat, W_ni,   cN, 0);
    node_gemm_k<<<GB, 256, SMEM_GEMM>>>(feat, W_nj,   cN, 64);
    node_gemm_k<<<GB, 256, SMEM_GEMM>>>(feat, W_node, cN, 128);
    edge_k<<<cE / 64, 256, SMEM_EDGE>>>(ew, src, dst, W_fij, attn, bias_e, 1);
    agg_k<<<cN / 8, 256>>>(src, 0);

    // ---- layer 1 (h = g_h1, w = g_w1) ----
    node_gemm_k<<<GB, 256, SMEM_GEMM>>>(nullptr, W_ni + 16384,   cN, 0);
    node_gemm_k<<<GB, 256, SMEM_GEMM>>>(nullptr, W_nj + 16384,   cN, 64);
    node_gemm_k<<<GB, 256, SMEM_GEMM>>>(nullptr, W_node + 16384, cN, 128);
    edge_k<<<cE / 64, 256, SMEM_EDGE>>>(nullptr, src, dst, W_fij + 16384,
                                        attn + 256, bias_e + 256, 0);
    agg_k<<<cN / 8, 256>>>(src, 1);

    // ---- JK concat pooling + linear ----
    pool_k<<<cB * 32, 192>>>(feat);
    final_k<<<1, 32>>>(W_lin, b_lin, out);
}

// round 6
// speedup vs baseline: 1.4425x; 1.4399x over previous
#include <cuda_runtime.h>
#include <cstdint>

// ---------------- problem constants ----------------
#define cN   50000
#define cE   800000
#define cB   8
#define cNPG 6250
#define LSLOPE 0.01f
#define NT_E 6250          // edge tiles of 128 (6250*128 == 800000)
#define NT_N 391           // node tiles of 128 (last partial)
#define PGRID 296          // persistent grid

// ---------------- scratch (device globals; no runtime allocation) ----------------
__device__ __align__(128) float g_HH[cN * 768];   // [ni(256)|nj(256)|n(256)] per node
__device__ __align__(128) float g_a[cE * 4];      // attention logits, CSR order
__device__ __align__(128) float g_w1[cE * 64];    // layer-0 edge feats (head mean), CSR order
__device__ __align__(128) float g_h1[cN * 64];
__device__ __align__(128) float g_h2[cN * 64];
__device__ __align__(128) float g_Wt[8 * 16384];  // transposed tf32 weights [n*64+k]
__device__ int   g_counts[cN];
__device__ int   g_rowptr[cN + 1];
__device__ int   g_cursor[cN];
__device__ int   g_csr[cE];
__device__ __align__(16) int g_srcp[cE];
__device__ __align__(16) int g_dstp[cE];
__device__ int   g_bsum[128];
__device__ float g_pooled[cB * 192];

// ---------------- helpers ----------------
__device__ __forceinline__ float to_tf32(float x) {
    uint32_t u;
    asm("cvt.rna.tf32.f32 %0, %1;" : "=r"(u) : "f"(x));
    return __uint_as_float(u);
}
__device__ __forceinline__ void mma_tf32(float* d, uint32_t a0, uint32_t a1,
                                         uint32_t a2, uint32_t a3,
                                         uint32_t b0, uint32_t b1) {
    asm volatile(
        "mma.sync.aligned.m16n8k8.row.col.f32.tf32.tf32.f32 "
        "{%0,%1,%2,%3}, {%4,%5,%6,%7}, {%8,%9}, {%0,%1,%2,%3};"
        : "+f"(d[0]), "+f"(d[1]), "+f"(d[2]), "+f"(d[3])
        : "r"(a0), "r"(a1), "r"(a2), "r"(a3), "r"(b0), "r"(b1));
}
__device__ __forceinline__ float4 add4(float4 a, float4 b) {
    return make_float4(a.x + b.x, a.y + b.y, a.z + b.z, a.w + b.w);
}
__device__ __forceinline__ float4 sub4(float4 a, float4 b) {
    return make_float4(a.x - b.x, a.y - b.y, a.z - b.z, a.w - b.w);
}
__device__ __forceinline__ float4 max4(float4 a, float4 b) {
    return make_float4(fmaxf(a.x, b.x), fmaxf(a.y, b.y), fmaxf(a.z, b.z), fmaxf(a.w, b.w));
}
__device__ __forceinline__ float4 exp4(float4 a) {
    return make_float4(__expf(a.x), __expf(a.y), __expf(a.z), __expf(a.w));
}
__device__ __forceinline__ float4 shflxor4(float4 v, int m) {
    v.x = __shfl_xor_sync(0xffffffffu, v.x, m);
    v.y = __shfl_xor_sync(0xffffffffu, v.y, m);
    v.z = __shfl_xor_sync(0xffffffffu, v.z, m);
    v.w = __shfl_xor_sync(0xffffffffu, v.w, m);
    return v;
}

// k-interleaved smem layout:
//   row stride = 72 floats; within each 8-wide k-group, element q (0..7) goes to
//   slot 2*(q&3) + (q>>2).  Fragment loads then read (k=t, k=t+4) as one float2
//   at offset kk*8 + 2t, conflict-free under stride 72 (banks 8g+2t distinct
//   within each 16-lane LDS.64 phase).
#define RSTRIDE 72

// ---------------- CSR build ----------------
__global__ void zero_k() {
    int i = blockIdx.x * 256 + threadIdx.x;
    if (i < cN) g_counts[i] = 0;
    if (i < cB * 192) g_pooled[i] = 0.f;
}
__global__ void hist_k(const int* __restrict__ dst) {
    int i = blockIdx.x * 256 + threadIdx.x;
    if (i < cE) atomicAdd(&g_counts[dst[i]], 1);
}
__global__ void scan1_k() {
    __shared__ int sh[512];
    int tid = threadIdx.x;
    int idx = blockIdx.x * 512 + tid;
    int v = (idx < cN) ? g_counts[idx] : 0;
    sh[tid] = v;
    __syncthreads();
    for (int off = 1; off < 512; off <<= 1) {
        int t = (tid >= off) ? sh[tid - off] : 0;
        __syncthreads();
        sh[tid] += t;
        __syncthreads();
    }
    if (idx < cN) g_rowptr[idx] = sh[tid] - v;
    if (tid == 511) g_bsum[blockIdx.x] = sh[511];
}
__global__ void scan2_k() {
    if (threadIdx.x == 0) {
        int run = 0;
        for (int i = 0; i < 98; i++) { int t = g_bsum[i]; g_bsum[i] = run; run += t; }
    }
}
__global__ void scan3_k() {
    int idx = blockIdx.x * 256 + threadIdx.x;
    if (idx < cN) {
        int v = g_rowptr[idx] + g_bsum[idx >> 9];
        g_rowptr[idx] = v;
        g_cursor[idx] = v;
    }
    if (idx == 0) g_rowptr[cN] = cE;
}
__global__ void scat_k(const int* __restrict__ src, const int* __restrict__ dst) {
    int i = blockIdx.x * 256 + threadIdx.x;
    if (i < cE) {
        int d = dst[i];
        int pos = atomicAdd(&g_cursor[d], 1);
        g_csr[pos] = i;
        g_srcp[pos] = src[i];
        g_dstp[pos] = d;
    }
}

// ---------------- weight transpose + tf32 round ----------------
// g_Wt[m][n*64+k] = tf32(W_m[k*256+n]); m = pair*2 + layer
// pair: 0=fij, 1=ni, 2=nj, 3=node
__global__ void prep_k(const float* __restrict__ fij, const float* __restrict__ ni,
                       const float* __restrict__ nj, const float* __restrict__ nd) {
    int i = blockIdx.x * 256 + threadIdx.x;
    if (i >= 8 * 16384) return;
    int m = i >> 14, r = i & 16383, n = r >> 6, k = r & 63;
    int pair = m >> 1;
    const float* base = (pair == 0) ? fij : (pair == 1) ? ni : (pair == 2) ? nj : nd;
    g_Wt[i] = to_tf32(base[(m & 1) * 16384 + k * 256 + n]);
}

// ---------------- node GEMM: (128 nodes, 64) @ (64, 256) -> g_HH section ----------------
__global__ void __launch_bounds__(256, 2)
node_mma_k(const float* __restrict__ Asrc, int widx, int sec) {
    extern __shared__ __align__(16) float sm[];
    float* As = sm;                      // 128*72
    float* Bs = sm + 128 * RSTRIDE;      // 256*72
    int tid = threadIdx.x, w = tid >> 5, lane = tid & 31;
    int g = lane >> 2, t = lane & 3;

    const float4* Wt4 = (const float4*)(g_Wt + widx * 16384);
    for (int i = tid; i < 4096; i += 256) {
        int n = i >> 4, c4 = i & 15;
        float4 v = Wt4[i];
        float* dp = Bs + n * RSTRIDE + (c4 >> 1) * 8 + (c4 & 1);
        dp[0] = v.x; dp[2] = v.y; dp[4] = v.z; dp[6] = v.w;
    }
    const float* A = Asrc ? Asrc : g_h1;

    for (int tile = blockIdx.x; tile < NT_N; tile += gridDim.x) {
        __syncthreads();
        for (int i = tid; i < 2048; i += 256) {
            int r = i >> 4, c4 = i & 15;
            int node = tile * 128 + r;
            float4 v = make_float4(0.f, 0.f, 0.f, 0.f);
            if (node < cN) v = ((const float4*)(A + (size_t)node * 64))[c4];
            v.x = to_tf32(v.x); v.y = to_tf32(v.y);
            v.z = to_tf32(v.z); v.w = to_tf32(v.w);
            float* dp = As + r * RSTRIDE + (c4 >> 1) * 8 + (c4 & 1);
            dp[0] = v.x; dp[2] = v.y; dp[4] = v.z; dp[6] = v.w;
        }
        __syncthreads();

#pragma unroll 1
        for (int p = 0; p < 2; p++) {
            float acc[16][4];
#pragma unroll
            for (int j = 0; j < 16; j++) {
                acc[j][0] = 0.f; acc[j][1] = 0.f; acc[j][2] = 0.f; acc[j][3] = 0.f;
            }
#pragma unroll
            for (int kk = 0; kk < 8; kk++) {
                const float* ap = As + (w * 16 + g) * RSTRIDE + kk * 8 + 2 * t;
                float2 lo = *(const float2*)ap;
                float2 hi = *(const float2*)(ap + 8 * RSTRIDE);
                uint32_t a0 = __float_as_uint(lo.x), a1 = __float_as_uint(hi.x);
                uint32_t a2 = __float_as_uint(lo.y), a3 = __float_as_uint(hi.y);
#pragma unroll
                for (int j = 0; j < 16; j++) {
                    const float* bp = Bs + (p * 128 + j * 8 + g) * RSTRIDE + kk * 8 + 2 * t;
                    float2 bb = *(const float2*)bp;
                    mma_tf32(acc[j], a0, a1, a2, a3,
                             __float_as_uint(bb.x), __float_as_uint(bb.y));
                }
            }
#pragma unroll
            for (int half = 0; half < 2; half++) {
                int r = w * 16 + g + half * 8;
                int node = tile * 128 + r;
                if (node < cN) {
                    float* op = g_HH + (size_t)node * 768 + sec;
#pragma unroll
                    for (int j = 0; j < 16; j++)
                        *(float2*)(op + p * 128 + j * 8 + 2 * t) =
                            make_float2(acc[j][half * 2], acc[j][half * 2 + 1]);
                }
            }
        }
    }
}

// ---------------- fused edge kernel ----------------
// per edge (CSR order): f = w@Wf + HHni[src] + HHnj[dst] + bias ; e = leaky(f)
// g_a[pos][h] = <e[h,:], attn[h,:]> ; layer0: g_w1[pos][:] = mean_h e[h,:]
__global__ void __launch_bounds__(256)
edge_mma_k(const float* __restrict__ Aew, const float* __restrict__ attn,
           const float* __restrict__ bias, int layer, int widx) {
    extern __shared__ __align__(16) float sm[];
    float* As = sm;                        // 128*72
    float* Bs = sm + 128 * RSTRIDE;        // 256*72
    float* bias_s = sm + 384 * RSTRIDE;    // 256
    float* attn_s = bias_s + 256;          // 256
    int tid = threadIdx.x, w = tid >> 5, lane = tid & 31;
    int g = lane >> 2, t = lane & 3;

    const float4* Wt4 = (const float4*)(g_Wt + widx * 16384);
    for (int i = tid; i < 4096; i += 256) {
        int n = i >> 4, c4 = i & 15;
        float4 v = Wt4[i];
        float* dp = Bs + n * RSTRIDE + (c4 >> 1) * 8 + (c4 & 1);
        dp[0] = v.x; dp[2] = v.y; dp[4] = v.z; dp[6] = v.w;
    }
    bias_s[tid] = bias[tid];
    attn_s[tid] = attn[tid];

    for (int tile = blockIdx.x; tile < NT_E; tile += gridDim.x) {
        __syncthreads();
        for (int i = tid; i < 2048; i += 256) {
            int r = i >> 4, c4 = i & 15;
            int pos = tile * 128 + r;
            const float4* srow = (layer == 0)
                ? (const float4*)(Aew + (size_t)g_csr[pos] * 64)
                : (const float4*)(g_w1 + (size_t)pos * 64);
            float4 v = srow[c4];
            v.x = to_tf32(v.x); v.y = to_tf32(v.y);
            v.z = to_tf32(v.z); v.w = to_tf32(v.w);
            float* dp = As + r * RSTRIDE + (c4 >> 1) * 8 + (c4 & 1);
            dp[0] = v.x; dp[2] = v.y; dp[4] = v.z; dp[6] = v.w;
        }
        __syncthreads();

        float stg[32];
#pragma unroll 1
        for (int p = 0; p < 2; p++) {
            float acc[16][4];
#pragma unroll
            for (int j = 0; j < 16; j++) {
                acc[j][0] = 0.f; acc[j][1] = 0.f; acc[j][2] = 0.f; acc[j][3] = 0.f;
            }
#pragma unroll
            for (int kk = 0; kk < 8; kk++) {
                const float* ap = As + (w * 16 + g) * RSTRIDE + kk * 8 + 2 * t;
                float2 lo = *(const float2*)ap;
                float2 hi = *(const float2*)(ap + 8 * RSTRIDE);
                uint32_t a0 = __float_as_uint(lo.x), a1 = __float_as_uint(hi.x);
                uint32_t a2 = __float_as_uint(lo.y), a3 = __float_as_uint(hi.y);
#pragma unroll
                for (int j = 0; j < 16; j++) {
                    const float* bp = Bs + (p * 128 + j * 8 + g) * RSTRIDE + kk * 8 + 2 * t;
                    float2 bb = *(const float2*)bp;
                    mma_tf32(acc[j], a0, a1, a2, a3,
                             __float_as_uint(bb.x), __float_as_uint(bb.y));
                }
            }
            // epilogue: heads 2p (cols p*128+[0,64)) and 2p+1 (cols p*128+[64,128))
#pragma unroll
            for (int half = 0; half < 2; half++) {
                int r = w * 16 + g + half * 8;
                int pos = tile * 128 + r;
                int se = g_srcp[pos], de = g_dstp[pos];
                const float* nip = g_HH + (size_t)se * 768;
                const float* njp = g_HH + (size_t)de * 768 + 256;
                float aacc0 = 0.f, aacc1 = 0.f;
#pragma unroll
                for (int j = 0; j < 8; j++) {
                    int c0 = p * 128 + j * 8 + 2 * t;   // head 2p
                    int c1 = c0 + 64;                   // head 2p+1
                    float2 u0 = *(const float2*)(nip + c0);
                    float2 v0 = *(const float2*)(njp + c0);
                    float2 bi0 = *(const float2*)(bias_s + c0);
                    float2 at0 = *(const float2*)(attn_s + c0);
                    float f00 = acc[j][half * 2]     + u0.x + v0.x + bi0.x;
                    float f01 = acc[j][half * 2 + 1] + u0.y + v0.y + bi0.y;
                    f00 = f00 > 0.f ? f00 : LSLOPE * f00;
                    f01 = f01 > 0.f ? f01 : LSLOPE * f01;
                    aacc0 += at0.x * f00 + at0.y * f01;
                    float2 u1 = *(const float2*)(nip + c1);
                    float2 v1 = *(const float2*)(njp + c1);
                    float2 bi1 = *(const float2*)(bias_s + c1);
                    float2 at1 = *(const float2*)(attn_s + c1);
                    float f10 = acc[j + 8][half * 2]     + u1.x + v1.x + bi1.x;
                    float f11 = acc[j + 8][half * 2 + 1] + u1.y + v1.y + bi1.y;
                    f10 = f10 > 0.f ? f10 : LSLOPE * f10;
                    f11 = f11 > 0.f ? f11 : LSLOPE * f11;
                    aacc1 += at1.x * f10 + at1.y * f11;
                    if (layer == 0) {
                        int sidx = (half * 8 + j) * 2;
                        float s0 = f00 + f10, s1 = f01 + f11;
                        if (p == 0) { stg[sidx] = s0; stg[sidx + 1] = s1; }
                        else {
                            *(float2*)(g_w1 + (size_t)pos * 64 + j * 8 + 2 * t) =
                                make_float2((stg[sidx] + s0) * 0.25f,
                                            (stg[sidx + 1] + s1) * 0.25f);
                        }
                    }
                }
                aacc0 += __shfl_xor_sync(0xffffffffu, aacc0, 1);
                aacc0 += __shfl_xor_sync(0xffffffffu, aacc0, 2);
                aacc1 += __shfl_xor_sync(0xffffffffu, aacc1, 1);
                aacc1 += __shfl_xor_sync(0xffffffffu, aacc1, 2);
                if (t == 0) {
                    g_a[(size_t)pos * 4 + 2 * p]     = aacc0;
                    g_a[(size_t)pos * 4 + 2 * p + 1] = aacc1;
                }
            }
        }
    }
}

// ---------------- softmax + aggregation (warp per dst node, CSR-contiguous) --------
__global__ void __launch_bounds__(256) agg_k(int layer) {
    int lane = threadIdx.x & 31, warp = threadIdx.x >> 5;
    int node = blockIdx.x * 8 + warp;
    float* hout = layer ? g_h2 : g_h1;
    float4* out4 = (float4*)(hout + (size_t)node * 64);
    int base = g_rowptr[node];
    int deg = g_rowptr[node + 1] - base;
    if (deg == 0) {
        if (lane < 16) out4[lane] = make_float4(0.f, 0.f, 0.f, 0.f);
        return;
    }
    const float4* a4 = (const float4*)g_a;
    float4 m = make_float4(-3.0e38f, -3.0e38f, -3.0e38f, -3.0e38f);
    for (int j = lane; j < deg; j += 32) m = max4(m, a4[base + j]);
#pragma unroll
    for (int off = 16; off >= 1; off >>= 1) m = max4(m, shflxor4(m, off));
    float4 ss = make_float4(0.f, 0.f, 0.f, 0.f);
    for (int j = lane; j < deg; j += 32) ss = add4(ss, exp4(sub4(a4[base + j], m)));
#pragma unroll
    for (int off = 16; off >= 1; off >>= 1) ss = add4(ss, shflxor4(ss, off));
    float4 inv = make_float4(1.f / ss.x, 1.f / ss.y, 1.f / ss.z, 1.f / ss.w);

    float4 accA = make_float4(0.f, 0.f, 0.f, 0.f);
    float4 accB = make_float4(0.f, 0.f, 0.f, 0.f);
    for (int j = 0; j < deg; j++) {
        int s = g_srcp[base + j];
        float4 av = a4[base + j];
        float4 wv = exp4(sub4(av, m));
        wv.x *= inv.x; wv.y *= inv.y; wv.z *= inv.z; wv.w *= inv.w;
        float wA = (lane < 16) ? wv.x : wv.y;
        float wB = (lane < 16) ? wv.z : wv.w;
        const float4* hn = (const float4*)(g_HH + (size_t)s * 768);
        float4 vA = hn[128 + lane], vB = hn[160 + lane];
        accA.x = fmaf(wA, vA.x, accA.x); accA.y = fmaf(wA, vA.y, accA.y);
        accA.z = fmaf(wA, vA.z, accA.z); accA.w = fmaf(wA, vA.w, accA.w);
        accB.x = fmaf(wB, vB.x, accB.x); accB.y = fmaf(wB, vB.y, accB.y);
        accB.z = fmaf(wB, vB.z, accB.z); accB.w = fmaf(wB, vB.w, accB.w);
    }
    float4 t4 = add4(accA, accB);
    t4.x += __shfl_down_sync(0xffffffffu, t4.x, 16);
    t4.y += __shfl_down_sync(0xffffffffu, t4.y, 16);
    t4.z += __shfl_down_sync(0xffffffffu, t4.z, 16);
    t4.w += __shfl_down_sync(0xffffffffu, t4.w, 16);
    if (lane < 16)
        out4[lane] = make_float4(t4.x * 0.25f, t4.y * 0.25f, t4.z * 0.25f, t4.w * 0.25f);
}

// ---------------- pooling + classifier ----------------
__global__ void pool_k(const float* __restrict__ feat) {
    int g = blockIdx.x >> 5, sub = blockIdx.x & 31;
    int n0 = sub * 196;
    int n1 = n0 + 196; if (n1 > cNPG) n1 = cNPG;
    int t = threadIdx.x;  // 0..191
    float sum = 0.f;
    for (int n = n0; n < n1; n++) {
        int gn = g * cNPG + n;
        float v;
        if (t < 64)       v = feat[(size_t)gn * 64 + t];
        else if (t < 128) v = g_h1[(size_t)gn * 64 + (t - 64)];
        else              v = g_h2[(size_t)gn * 64 + (t - 128)];
        sum += v;
    }
    atomicAdd(&g_pooled[g * 192 + t], sum);
}
__global__ void final_k(const float* __restrict__ Wlin, const float* __restrict__ blin,
                        float* __restrict__ out) {
    int t = threadIdx.x;
    if (t < 16) {
        int b = t >> 1, c = t & 1;
        float acc = blin[c];
        const float invn = 1.0f / (float)cNPG;
        for (int k = 0; k < 192; k++)
            acc += (g_pooled[b * 192 + k] * invn) * Wlin[k * 2 + c];
        out[t] = acc;
    }
}

// ---------------- launch ----------------
extern "C" void kernel_launch(void* const* d_in, const int* in_sizes, int n_in,
                              void* d_out, int out_size) {
    const float* feat   = (const float*)d_in[0];
    const float* ew     = (const float*)d_in[1];
    const int*   src    = (const int*)d_in[2];
    const int*   dst    = (const int*)d_in[3];
    const float* W_node = (const float*)d_in[4];
    const float* W_ni   = (const float*)d_in[5];
    const float* W_nj   = (const float*)d_in[6];
    const float* W_fij  = (const float*)d_in[7];
    const float* attn   = (const float*)d_in[8];
    const float* bias_e = (const float*)d_in[9];
    const float* W_lin  = (const float*)d_in[10];
    const float* b_lin  = (const float*)d_in[11];
    float* out = (float*)d_out;

    const int NSMEM = 384 * RSTRIDE * 4;          // 110592
    const int ESMEM = 384 * RSTRIDE * 4 + 2048;   // 112640
    cudaFuncSetAttribute((const void*)node_mma_k,
                         cudaFuncAttributeMaxDynamicSharedMemorySize, NSMEM);
    cudaFuncSetAttribute((const void*)edge_mma_k,
                         cudaFuncAttributeMaxDynamicSharedMemorySize, ESMEM);

    // CSR build + weight prep
    zero_k<<<(cN + 255) / 256, 256>>>();
    hist_k<<<(cE + 255) / 256, 256>>>(dst);
    scan1_k<<<98, 512>>>();
    scan2_k<<<1, 32>>>();
    scan3_k<<<(cN + 255) / 256, 256>>>();
    scat_k<<<(cE + 255) / 256, 256>>>(src, dst);
    prep_k<<<512, 256>>>(W_fij, W_ni, W_nj, W_node);

    // ---- layer 0 ----
    node_mma_k<<<PGRID, 256, NSMEM>>>(feat, 2, 0);     // ni0
    node_mma_k<<<PGRID, 256, NSMEM>>>(feat, 4, 256);   // nj0
    node_mma_k<<<PGRID, 256, NSMEM>>>(feat, 6, 512);   // node0
    edge_mma_k<<<PGRID, 256, ESMEM>>>(ew, attn, bias_e, 0, 0);
    agg_k<<<cN / 8, 256>>>(0);

    // ---- layer 1 ----
    node_mma_k<<<PGRID, 256, NSMEM>>>(nullptr, 3, 0);   // ni1
    node_mma_k<<<PGRID, 256, NSMEM>>>(nullptr, 5, 256); // nj1
    node_mma_k<<<PGRID, 256, NSMEM>>>(nullptr, 7, 512); // node1
    edge_mma_k<<<PGRID, 256, ESMEM>>>(ew, attn + 256, bias_e + 256, 1, 1);
    agg_k<<<cN / 8, 256>>>(1);

    // ---- JK pooling + classifier ----
    pool_k<<<cB * 32, 192>>>(feat);
    final_k<<<1, 32>>>(W_lin, b_lin, out);
}

// round 7
// speedup vs baseline: 1.7203x; 1.1926x over previous
#include <cuda_runtime.h>
#include <cuda_fp16.h>
#include <cstdint>

// ---------------- problem constants ----------------
#define cN   50000
#define cE   800000
#define cB   8
#define cNPG 6250
#define LSLOPE 0.01f
#define NT_E 6250          // edge tiles of 128 (6250*128 == 800000)
#define NT_N 391           // node tiles of 128 (last partial)
#define PGRID 296          // persistent grid

// ---------------- scratch (device globals; no runtime allocation) ----------------
__device__ __align__(128) __half g_HH[cN * 768];  // fp16 [ni(256)|nj(256)|n(256)] per node
__device__ __align__(128) float  g_a[cE * 4];     // attention logits, CSR order
__device__ __align__(128) __half g_w1[cE * 64];   // fp16 layer-0 edge feats, CSR order
__device__ __align__(128) float  g_h1[cN * 64];
__device__ __align__(128) float  g_h2[cN * 64];
__device__ __align__(128) float  g_Wt[8 * 16384]; // transposed tf32 weights [n*64+k]
__device__ int   g_counts[cN];
__device__ int   g_rowptr[cN + 1];
__device__ int   g_cursor[cN];
__device__ int   g_csr[cE];
__device__ __align__(16) int g_srcp[cE];
__device__ __align__(16) int g_dstp[cE];
__device__ int   g_bsum[128];
__device__ float g_pooled[cB * 192];

// ---------------- helpers ----------------
__device__ __forceinline__ float to_tf32(float x) {
    uint32_t u;
    asm("cvt.rna.tf32.f32 %0, %1;" : "=r"(u) : "f"(x));
    return __uint_as_float(u);
}
__device__ __forceinline__ void mma_tf32(float* d, uint32_t a0, uint32_t a1,
                                         uint32_t a2, uint32_t a3,
                                         uint32_t b0, uint32_t b1) {
    asm volatile(
        "mma.sync.aligned.m16n8k8.row.col.f32.tf32.tf32.f32 "
        "{%0,%1,%2,%3}, {%4,%5,%6,%7}, {%8,%9}, {%0,%1,%2,%3};"
        : "+f"(d[0]), "+f"(d[1]), "+f"(d[2]), "+f"(d[3])
        : "r"(a0), "r"(a1), "r"(a2), "r"(a3), "r"(b0), "r"(b1));
}
__device__ __forceinline__ float4 add4(float4 a, float4 b) {
    return make_float4(a.x + b.x, a.y + b.y, a.z + b.z, a.w + b.w);
}
__device__ __forceinline__ float4 sub4(float4 a, float4 b) {
    return make_float4(a.x - b.x, a.y - b.y, a.z - b.z, a.w - b.w);
}
__device__ __forceinline__ float4 max4(float4 a, float4 b) {
    return make_float4(fmaxf(a.x, b.x), fmaxf(a.y, b.y), fmaxf(a.z, b.z), fmaxf(a.w, b.w));
}
__device__ __forceinline__ float4 exp4(float4 a) {
    return make_float4(__expf(a.x), __expf(a.y), __expf(a.z), __expf(a.w));
}
__device__ __forceinline__ float4 shflxor4(float4 v, int m) {
    v.x = __shfl_xor_sync(0xffffffffu, v.x, m);
    v.y = __shfl_xor_sync(0xffffffffu, v.y, m);
    v.z = __shfl_xor_sync(0xffffffffu, v.z, m);
    v.w = __shfl_xor_sync(0xffffffffu, v.w, m);
    return v;
}

// k-interleaved smem layout: row stride 72 floats; within each 8-wide k-group,
// element q goes to slot 2*(q&3)+(q>>2); fragment loads are conflict-free float2.
#define RSTRIDE 72

// ---------------- CSR build ----------------
__global__ void zero_k() {
    int i = blockIdx.x * 256 + threadIdx.x;
    if (i < cN) g_counts[i] = 0;
    if (i < cB * 192) g_pooled[i] = 0.f;
}
__global__ void hist_k(const int* __restrict__ dst) {
    int i = blockIdx.x * 256 + threadIdx.x;
    if (i < cE) atomicAdd(&g_counts[dst[i]], 1);
}
__global__ void scan1_k() {
    __shared__ int sh[512];
    int tid = threadIdx.x;
    int idx = blockIdx.x * 512 + tid;
    int v = (idx < cN) ? g_counts[idx] : 0;
    sh[tid] = v;
    __syncthreads();
    for (int off = 1; off < 512; off <<= 1) {
        int t = (tid >= off) ? sh[tid - off] : 0;
        __syncthreads();
        sh[tid] += t;
        __syncthreads();
    }
    if (idx < cN) g_rowptr[idx] = sh[tid] - v;
    if (tid == 511) g_bsum[blockIdx.x] = sh[511];
}
__global__ void scan2_k() {
    if (threadIdx.x == 0) {
        int run = 0;
        for (int i = 0; i < 98; i++) { int t = g_bsum[i]; g_bsum[i] = run; run += t; }
    }
}
__global__ void scan3_k() {
    int idx = blockIdx.x * 256 + threadIdx.x;
    if (idx < cN) {
        int v = g_rowptr[idx] + g_bsum[idx >> 9];
        g_rowptr[idx] = v;
        g_cursor[idx] = v;
    }
    if (idx == 0) g_rowptr[cN] = cE;
}
__global__ void scat_k(const int* __restrict__ src, const int* __restrict__ dst) {
    int i = blockIdx.x * 256 + threadIdx.x;
    if (i < cE) {
        int d = dst[i];
        int pos = atomicAdd(&g_cursor[d], 1);
        g_csr[pos] = i;
        g_srcp[pos] = src[i];
        g_dstp[pos] = d;
    }
}

// ---------------- weight transpose + tf32 round ----------------
__global__ void prep_k(const float* __restrict__ fij, const float* __restrict__ ni,
                       const float* __restrict__ nj, const float* __restrict__ nd) {
    int i = blockIdx.x * 256 + threadIdx.x;
    if (i >= 8 * 16384) return;
    int m = i >> 14, r = i & 16383, n = r >> 6, k = r & 63;
    int pair = m >> 1;
    const float* base = (pair == 0) ? fij : (pair == 1) ? ni : (pair == 2) ? nj : nd;
    g_Wt[i] = to_tf32(base[(m & 1) * 16384 + k * 256 + n]);
}

// ---------------- node GEMM: (128 nodes, 64) @ (64, 256) -> g_HH section (fp16) -------
__global__ void __launch_bounds__(256, 2)
node_mma_k(const float* __restrict__ Asrc, int widx, int sec) {
    extern __shared__ __align__(16) float sm[];
    float* As = sm;                      // 128*72
    float* Bs = sm + 128 * RSTRIDE;      // 256*72
    int tid = threadIdx.x, w = tid >> 5, lane = tid & 31;
    int g = lane >> 2, t = lane & 3;

    const float4* Wt4 = (const float4*)(g_Wt + widx * 16384);
    for (int i = tid; i < 4096; i += 256) {
        int n = i >> 4, c4 = i & 15;
        float4 v = Wt4[i];
        float* dp = Bs + n * RSTRIDE + (c4 >> 1) * 8 + (c4 & 1);
        dp[0] = v.x; dp[2] = v.y; dp[4] = v.z; dp[6] = v.w;
    }
    const float* A = Asrc ? Asrc : g_h1;

    for (int tile = blockIdx.x; tile < NT_N; tile += gridDim.x) {
        __syncthreads();
        for (int i = tid; i < 2048; i += 256) {
            int r = i >> 4, c4 = i & 15;
            int node = tile * 128 + r;
            float4 v = make_float4(0.f, 0.f, 0.f, 0.f);
            if (node < cN) v = ((const float4*)(A + (size_t)node * 64))[c4];
            v.x = to_tf32(v.x); v.y = to_tf32(v.y);
            v.z = to_tf32(v.z); v.w = to_tf32(v.w);
            float* dp = As + r * RSTRIDE + (c4 >> 1) * 8 + (c4 & 1);
            dp[0] = v.x; dp[2] = v.y; dp[4] = v.z; dp[6] = v.w;
        }
        __syncthreads();

#pragma unroll 1
        for (int p = 0; p < 2; p++) {
            float acc[16][4];
#pragma unroll
            for (int j = 0; j < 16; j++) {
                acc[j][0] = 0.f; acc[j][1] = 0.f; acc[j][2] = 0.f; acc[j][3] = 0.f;
            }
#pragma unroll
            for (int kk = 0; kk < 8; kk++) {
                const float* ap = As + (w * 16 + g) * RSTRIDE + kk * 8 + 2 * t;
                float2 lo = *(const float2*)ap;
                float2 hi = *(const float2*)(ap + 8 * RSTRIDE);
                uint32_t a0 = __float_as_uint(lo.x), a1 = __float_as_uint(hi.x);
                uint32_t a2 = __float_as_uint(lo.y), a3 = __float_as_uint(hi.y);
#pragma unroll
                for (int j = 0; j < 16; j++) {
                    const float* bp = Bs + (p * 128 + j * 8 + g) * RSTRIDE + kk * 8 + 2 * t;
                    float2 bb = *(const float2*)bp;
                    mma_tf32(acc[j], a0, a1, a2, a3,
                             __float_as_uint(bb.x), __float_as_uint(bb.y));
                }
            }
#pragma unroll
            for (int half = 0; half < 2; half++) {
                int r = w * 16 + g + half * 8;
                int node = tile * 128 + r;
                if (node < cN) {
                    __half* op = g_HH + (size_t)node * 768 + sec;
#pragma unroll
                    for (int j = 0; j < 16; j++)
                        *(__half2*)(op + p * 128 + j * 8 + 2 * t) =
                            __floats2half2_rn(acc[j][half * 2], acc[j][half * 2 + 1]);
                }
            }
        }
    }
}

// ---------------- fused edge kernel (fp16 gathers) ----------------
__global__ void __launch_bounds__(256)
edge_mma_k(const float* __restrict__ Aew, const float* __restrict__ attn,
           const float* __restrict__ bias, int layer, int widx) {
    extern __shared__ __align__(16) float sm[];
    float* As = sm;                        // 128*72
    float* Bs = sm + 128 * RSTRIDE;        // 256*72
    float* bias_s = sm + 384 * RSTRIDE;    // 256
    float* attn_s = bias_s + 256;          // 256
    int tid = threadIdx.x, w = tid >> 5, lane = tid & 31;
    int g = lane >> 2, t = lane & 3;

    const float4* Wt4 = (const float4*)(g_Wt + widx * 16384);
    for (int i = tid; i < 4096; i += 256) {
        int n = i >> 4, c4 = i & 15;
        float4 v = Wt4[i];
        float* dp = Bs + n * RSTRIDE + (c4 >> 1) * 8 + (c4 & 1);
        dp[0] = v.x; dp[2] = v.y; dp[4] = v.z; dp[6] = v.w;
    }
    bias_s[tid] = bias[tid];
    attn_s[tid] = attn[tid];

    for (int tile = blockIdx.x; tile < NT_E; tile += gridDim.x) {
        __syncthreads();
        for (int i = tid; i < 2048; i += 256) {
            int r = i >> 4, c4 = i & 15;
            int pos = tile * 128 + r;
            float4 v;
            if (layer == 0) {
                v = ((const float4*)(Aew + (size_t)g_csr[pos] * 64))[c4];
                v.x = to_tf32(v.x); v.y = to_tf32(v.y);
                v.z = to_tf32(v.z); v.w = to_tf32(v.w);
            } else {
                // fp16 -> fp32 is exact and already within tf32 mantissa
                uint2 u = ((const uint2*)(g_w1 + (size_t)pos * 64))[c4];
                float2 fa = __half22float2(*(__half2*)&u.x);
                float2 fb = __half22float2(*(__half2*)&u.y);
                v = make_float4(fa.x, fa.y, fb.x, fb.y);
            }
            float* dp = As + r * RSTRIDE + (c4 >> 1) * 8 + (c4 & 1);
            dp[0] = v.x; dp[2] = v.y; dp[4] = v.z; dp[6] = v.w;
        }
        __syncthreads();

        float stg[32];
#pragma unroll 1
        for (int p = 0; p < 2; p++) {
            float acc[16][4];
#pragma unroll
            for (int j = 0; j < 16; j++) {
                acc[j][0] = 0.f; acc[j][1] = 0.f; acc[j][2] = 0.f; acc[j][3] = 0.f;
            }
#pragma unroll
            for (int kk = 0; kk < 8; kk++) {
                const float* ap = As + (w * 16 + g) * RSTRIDE + kk * 8 + 2 * t;
                float2 lo = *(const float2*)ap;
                float2 hi = *(const float2*)(ap + 8 * RSTRIDE);
                uint32_t a0 = __float_as_uint(lo.x), a1 = __float_as_uint(hi.x);
                uint32_t a2 = __float_as_uint(lo.y), a3 = __float_as_uint(hi.y);
#pragma unroll
                for (int j = 0; j < 16; j++) {
                    const float* bp = Bs + (p * 128 + j * 8 + g) * RSTRIDE + kk * 8 + 2 * t;
                    float2 bb = *(const float2*)bp;
                    mma_tf32(acc[j], a0, a1, a2, a3,
                             __float_as_uint(bb.x), __float_as_uint(bb.y));
                }
            }
            // epilogue: heads 2p (cols p*128+[0,64)) and 2p+1 (cols p*128+[64,128))
#pragma unroll
            for (int half = 0; half < 2; half++) {
                int r = w * 16 + g + half * 8;
                int pos = tile * 128 + r;
                int se = g_srcp[pos], de = g_dstp[pos];
                const __half* nip = g_HH + (size_t)se * 768;
                const __half* njp = g_HH + (size_t)de * 768 + 256;
                float aacc0 = 0.f, aacc1 = 0.f;
#pragma unroll
                for (int j = 0; j < 8; j++) {
                    int c0 = p * 128 + j * 8 + 2 * t;   // head 2p
                    int c1 = c0 + 64;                   // head 2p+1
                    float2 u0 = __half22float2(*(const __half2*)(nip + c0));
                    float2 v0 = __half22float2(*(const __half2*)(njp + c0));
                    float2 bi0 = *(const float2*)(bias_s + c0);
                    float2 at0 = *(const float2*)(attn_s + c0);
                    float f00 = acc[j][half * 2]     + u0.x + v0.x + bi0.x;
                    float f01 = acc[j][half * 2 + 1] + u0.y + v0.y + bi0.y;
                    f00 = f00 > 0.f ? f00 : LSLOPE * f00;
                    f01 = f01 > 0.f ? f01 : LSLOPE * f01;
                    aacc0 += at0.x * f00 + at0.y * f01;
                    float2 u1 = __half22float2(*(const __half2*)(nip + c1));
                    float2 v1 = __half22float2(*(const __half2*)(njp + c1));
                    float2 bi1 = *(const float2*)(bias_s + c1);
                    float2 at1 = *(const float2*)(attn_s + c1);
                    float f10 = acc[j + 8][half * 2]     + u1.x + v1.x + bi1.x;
                    float f11 = acc[j + 8][half * 2 + 1] + u1.y + v1.y + bi1.y;
                    f10 = f10 > 0.f ? f10 : LSLOPE * f10;
                    f11 = f11 > 0.f ? f11 : LSLOPE * f11;
                    aacc1 += at1.x * f10 + at1.y * f11;
                    if (layer == 0) {
                        int sidx = (half * 8 + j) * 2;
                        float s0 = f00 + f10, s1 = f01 + f11;
                        if (p == 0) { stg[sidx] = s0; stg[sidx + 1] = s1; }
                        else {
                            *(__half2*)(g_w1 + (size_t)pos * 64 + j * 8 + 2 * t) =
                                __floats2half2_rn((stg[sidx] + s0) * 0.25f,
                                                  (stg[sidx + 1] + s1) * 0.25f);
                        }
                    }
                }
                aacc0 += __shfl_xor_sync(0xffffffffu, aacc0, 1);
                aacc0 += __shfl_xor_sync(0xffffffffu, aacc0, 2);
                aacc1 += __shfl_xor_sync(0xffffffffu, aacc1, 1);
                aacc1 += __shfl_xor_sync(0xffffffffu, aacc1, 2);
                if (t == 0) {
                    g_a[(size_t)pos * 4 + 2 * p]     = aacc0;
                    g_a[(size_t)pos * 4 + 2 * p + 1] = aacc1;
                }
            }
        }
    }
}

// ---------------- softmax + aggregation (warp per dst node, fp16 gathers) ----------
__global__ void __launch_bounds__(256) agg_k(int layer) {
    int lane = threadIdx.x & 31, warp = threadIdx.x >> 5;
    int node = blockIdx.x * 8 + warp;
    float* hout = layer ? g_h2 : g_h1;
    float4* out4 = (float4*)(hout + (size_t)node * 64);
    int base = g_rowptr[node];
    int deg = g_rowptr[node + 1] - base;
    if (deg == 0) {
        if (lane < 16) out4[lane] = make_float4(0.f, 0.f, 0.f, 0.f);
        return;
    }
    const float4* a4 = (const float4*)g_a;
    float4 m = make_float4(-3.0e38f, -3.0e38f, -3.0e38f, -3.0e38f);
    for (int j = lane; j < deg; j += 32) m = max4(m, a4[base + j]);
#pragma unroll
    for (int off = 16; off >= 1; off >>= 1) m = max4(m, shflxor4(m, off));
    float4 ss = make_float4(0.f, 0.f, 0.f, 0.f);
    for (int j = lane; j < deg; j += 32) ss = add4(ss, exp4(sub4(a4[base + j], m)));
#pragma unroll
    for (int off = 16; off >= 1; off >>= 1) ss = add4(ss, shflxor4(ss, off));
    float4 inv = make_float4(1.f / ss.x, 1.f / ss.y, 1.f / ss.z, 1.f / ss.w);

    float4 accA = make_float4(0.f, 0.f, 0.f, 0.f);
    float4 accB = make_float4(0.f, 0.f, 0.f, 0.f);
    for (int j = 0; j < deg; j++) {
        int s = g_srcp[base + j];
        float4 av = a4[base + j];
        float4 wv = exp4(sub4(av, m));
        wv.x *= inv.x; wv.y *= inv.y; wv.z *= inv.z; wv.w *= inv.w;
        float wA = (lane < 16) ? wv.x : wv.y;
        float wB = (lane < 16) ? wv.z : wv.w;
        const __half* hn = g_HH + (size_t)s * 768 + 512;  // 'n' section
        uint2 ua = *(const uint2*)(hn + 4 * lane);
        uint2 ub = *(const uint2*)(hn + 128 + 4 * lane);
        float2 a0 = __half22float2(*(__half2*)&ua.x);
        float2 a1 = __half22float2(*(__half2*)&ua.y);
        float2 b0 = __half22float2(*(__half2*)&ub.x);
        float2 b1 = __half22float2(*(__half2*)&ub.y);
        accA.x = fmaf(wA, a0.x, accA.x); accA.y = fmaf(wA, a0.y, accA.y);
        accA.z = fmaf(wA, a1.x, accA.z); accA.w = fmaf(wA, a1.y, accA.w);
        accB.x = fmaf(wB, b0.x, accB.x); accB.y = fmaf(wB, b0.y, accB.y);
        accB.z = fmaf(wB, b1.x, accB.z); accB.w = fmaf(wB, b1.y, accB.w);
    }
    float4 t4 = add4(accA, accB);
    t4.x += __shfl_down_sync(0xffffffffu, t4.x, 16);
    t4.y += __shfl_down_sync(0xffffffffu, t4.y, 16);
    t4.z += __shfl_down_sync(0xffffffffu, t4.z, 16);
    t4.w += __shfl_down_sync(0xffffffffu, t4.w, 16);
    if (lane < 16)
        out4[lane] = make_float4(t4.x * 0.25f, t4.y * 0.25f, t4.z * 0.25f, t4.w * 0.25f);
}

// ---------------- pooling + classifier ----------------
__global__ void pool_k(const float* __restrict__ feat) {
    int g = blockIdx.x >> 5, sub = blockIdx.x & 31;
    int n0 = sub * 196;
    int n1 = n0 + 196; if (n1 > cNPG) n1 = cNPG;
    int t = threadIdx.x;  // 0..191
    float sum = 0.f;
    for (int n = n0; n < n1; n++) {
        int gn = g * cNPG + n;
        float v;
        if (t < 64)       v = feat[(size_t)gn * 64 + t];
        else if (t < 128) v = g_h1[(size_t)gn * 64 + (t - 64)];
        else              v = g_h2[(size_t)gn * 64 + (t - 128)];
        sum += v;
    }
    atomicAdd(&g_pooled[g * 192 + t], sum);
}
__global__ void final_k(const float* __restrict__ Wlin, const float* __restrict__ blin,
                        float* __restrict__ out) {
    int t = threadIdx.x;
    if (t < 16) {
        int b = t >> 1, c = t & 1;
        float acc = blin[c];
        const float invn = 1.0f / (float)cNPG;
        for (int k = 0; k < 192; k++)
            acc += (g_pooled[b * 192 + k] * invn) * Wlin[k * 2 + c];
        out[t] = acc;
    }
}

// ---------------- launch ----------------
extern "C" void kernel_launch(void* const* d_in, const int* in_sizes, int n_in,
                              void* d_out, int out_size) {
    const float* feat   = (const float*)d_in[0];
    const float* ew     = (const float*)d_in[1];
    const int*   src    = (const int*)d_in[2];
    const int*   dst    = (const int*)d_in[3];
    const float* W_node = (const float*)d_in[4];
    const float* W_ni   = (const float*)d_in[5];
    const float* W_nj   = (const float*)d_in[6];
    const float* W_fij  = (const float*)d_in[7];
    const float* attn   = (const float*)d_in[8];
    const float* bias_e = (const float*)d_in[9];
    const float* W_lin  = (const float*)d_in[10];
    const float* b_lin  = (const float*)d_in[11];
    float* out = (float*)d_out;

    const int NSMEM = 384 * RSTRIDE * 4;          // 110592
    const int ESMEM = 384 * RSTRIDE * 4 + 2048;   // 112640
    cudaFuncSetAttribute((const void*)node_mma_k,
                         cudaFuncAttributeMaxDynamicSharedMemorySize, NSMEM);
    cudaFuncSetAttribute((const void*)edge_mma_k,
                         cudaFuncAttributeMaxDynamicSharedMemorySize, ESMEM);

    // CSR build + weight prep
    zero_k<<<(cN + 255) / 256, 256>>>();
    hist_k<<<(cE + 255) / 256, 256>>>(dst);
    scan1_k<<<98, 512>>>();
    scan2_k<<<1, 32>>>();
    scan3_k<<<(cN + 255) / 256, 256>>>();
    scat_k<<<(cE + 255) / 256, 256>>>(src, dst);
    prep_k<<<512, 256>>>(W_fij, W_ni, W_nj, W_node);

    // ---- layer 0 ----
    node_mma_k<<<PGRID, 256, NSMEM>>>(feat, 2, 0);     // ni0
    node_mma_k<<<PGRID, 256, NSMEM>>>(feat, 4, 256);   // nj0
    node_mma_k<<<PGRID, 256, NSMEM>>>(feat, 6, 512);   // node0
    edge_mma_k<<<PGRID, 256, ESMEM>>>(ew, attn, bias_e, 0, 0);
    agg_k<<<cN / 8, 256>>>(0);

    // ---- layer 1 ----
    node_mma_k<<<PGRID, 256, NSMEM>>>(nullptr, 3, 0);   // ni1
    node_mma_k<<<PGRID, 256, NSMEM>>>(nullptr, 5, 256); // nj1
    node_mma_k<<<PGRID, 256, NSMEM>>>(nullptr, 7, 512); // node1
    edge_mma_k<<<PGRID, 256, ESMEM>>>(ew, attn + 256, bias_e + 256, 1, 1);
    agg_k<<<cN / 8, 256>>>(1);

    // ---- JK pooling + classifier ----
    pool_k<<<cB * 32, 192>>>(feat);
    final_k<<<1, 32>>>(W_lin, b_lin, out);
}

// round 9
// speedup vs baseline: 2.3518x; 1.3671x over previous
#include <cuda_runtime.h>
#include <cuda_fp16.h>
#include <cstdint>

// ---------------- problem constants ----------------
#define cN   50000
#define cE   800000
#define cB   8
#define cNPG 6250
#define LSLOPE 0.01f
#define NT_E 6250          // edge tiles of 128 (6250*128 == 800000)
#define NT_N 391           // node tiles of 128 (last partial)
#define PGRID 296          // persistent grid (2 blocks/SM)

// ---------------- scratch (device globals; no runtime allocation) ----------------
__device__ __align__(128) __half g_HH[cN * 768];  // fp16 [ni(256)|nj(256)|n(256)] per node
__device__ __align__(128) float  g_a[cE * 4];     // attention logits, CSR order
__device__ __align__(128) __half g_w1[cE * 64];   // fp16 layer-0 edge feats, CSR order
__device__ __align__(128) float  g_h1[cN * 64];
__device__ __align__(128) float  g_h2[cN * 64];
__device__ __align__(128) __half g_Wh[8 * 16384]; // transposed fp16 weights [n*64+k]
__device__ int   g_counts[cN];
__device__ int   g_rowptr[cN + 1];
__device__ int   g_cursor[cN];
__device__ int   g_csr[cE];
__device__ __align__(16) int g_srcp[cE];
__device__ __align__(16) int g_dstp[cE];
__device__ int   g_bsum[128];
__device__ float g_pooled[cB * 192];

// ---------------- helpers ----------------
__device__ __forceinline__ void mma_f16(float* d, uint32_t a0, uint32_t a1,
                                        uint32_t a2, uint32_t a3,
                                        uint32_t b0, uint32_t b1) {
    asm volatile(
        "mma.sync.aligned.m16n8k16.row.col.f32.f16.f16.f32 "
        "{%0,%1,%2,%3}, {%4,%5,%6,%7}, {%8,%9}, {%0,%1,%2,%3};"
        : "+f"(d[0]), "+f"(d[1]), "+f"(d[2]), "+f"(d[3])
        : "r"(a0), "r"(a1), "r"(a2), "r"(a3), "r"(b0), "r"(b1));
}
__device__ __forceinline__ float4 add4(float4 a, float4 b) {
    return make_float4(a.x + b.x, a.y + b.y, a.z + b.z, a.w + b.w);
}
__device__ __forceinline__ float4 sub4(float4 a, float4 b) {
    return make_float4(a.x - b.x, a.y - b.y, a.z - b.z, a.w - b.w);
}
__device__ __forceinline__ float4 max4(float4 a, float4 b) {
    return make_float4(fmaxf(a.x, b.x), fmaxf(a.y, b.y), fmaxf(a.z, b.z), fmaxf(a.w, b.w));
}
__device__ __forceinline__ float4 exp4(float4 a) {
    return make_float4(__expf(a.x), __expf(a.y), __expf(a.z), __expf(a.w));
}
__device__ __forceinline__ float4 shflxor4(float4 v, int m) {
    v.x = __shfl_xor_sync(0xffffffffu, v.x, m);
    v.y = __shfl_xor_sync(0xffffffffu, v.y, m);
    v.z = __shfl_xor_sync(0xffffffffu, v.z, m);
    v.w = __shfl_xor_sync(0xffffffffu, v.w, m);
    return v;
}

// smem tiles in fp16, row stride 72 halfs (144 B) -> bank (4g+t) mod 32, conflict-free
#define RSTRIDE 72

// ---------------- CSR build ----------------
__global__ void zero_k() {
    int i = blockIdx.x * 256 + threadIdx.x;
    if (i < cN) g_counts[i] = 0;
    if (i < cB * 192) g_pooled[i] = 0.f;
}
__global__ void hist_k(const int* __restrict__ dst) {
    int i = blockIdx.x * 256 + threadIdx.x;
    if (i < cE) atomicAdd(&g_counts[dst[i]], 1);
}
__global__ void scan1_k() {
    __shared__ int sh[512];
    int tid = threadIdx.x;
    int idx = blockIdx.x * 512 + tid;
    int v = (idx < cN) ? g_counts[idx] : 0;
    sh[tid] = v;
    __syncthreads();
    for (int off = 1; off < 512; off <<= 1) {
        int t = (tid >= off) ? sh[tid - off] : 0;
        __syncthreads();
        sh[tid] += t;
        __syncthreads();
    }
    if (idx < cN) g_rowptr[idx] = sh[tid] - v;
    if (tid == 511) g_bsum[blockIdx.x] = sh[511];
}
__global__ void scan2_k() {
    if (threadIdx.x == 0) {
        int run = 0;
        for (int i = 0; i < 98; i++) { int t = g_bsum[i]; g_bsum[i] = run; run += t; }
    }
}
__global__ void scan3_k() {
    int idx = blockIdx.x * 256 + threadIdx.x;
    if (idx < cN) {
        int v = g_rowptr[idx] + g_bsum[idx >> 9];
        g_rowptr[idx] = v;
        g_cursor[idx] = v;
    }
    if (idx == 0) g_rowptr[cN] = cE;
}
__global__ void scat_k(const int* __restrict__ src, const int* __restrict__ dst) {
    int i = blockIdx.x * 256 + threadIdx.x;
    if (i < cE) {
        int d = dst[i];
        int pos = atomicAdd(&g_cursor[d], 1);
        g_csr[pos] = i;
        g_srcp[pos] = src[i];
        g_dstp[pos] = d;
    }
}

// ---------------- weight transpose + fp16 round ----------------
// g_Wh[m][n*64+k] = fp16(W_m[k*256+n]); m = pair*2 + layer
__global__ void prep_k(const float* __restrict__ fij, const float* __restrict__ ni,
                       const float* __restrict__ nj, const float* __restrict__ nd) {
    int i = blockIdx.x * 256 + threadIdx.x;
    if (i >= 8 * 16384) return;
    int m = i >> 14, r = i & 16383, n = r >> 6, k = r & 63;
    int pair = m >> 1;
    const float* base = (pair == 0) ? fij : (pair == 1) ? ni : (pair == 2) ? nj : nd;
    g_Wh[i] = __float2half_rn(base[(m & 1) * 16384 + k * 256 + n]);
}

// ---------------- node GEMM: (128 nodes, 64) @ (64, 256) -> g_HH section (fp16) -------
__global__ void __launch_bounds__(256, 2)
node_mma_k(const float* __restrict__ Asrc, int widx, int sec) {
    extern __shared__ __align__(16) unsigned char smraw[];
    __half* As = (__half*)smraw;                    // 128*72 halfs
    __half* Bs = As + 128 * RSTRIDE;                // 256*72 halfs
    int tid = threadIdx.x, w = tid >> 5, lane = tid & 31;
    int g = lane >> 2, t = lane & 3;

    const uint4* Wh4 = (const uint4*)(g_Wh + widx * 16384);
    for (int i = tid; i < 2048; i += 256) {
        int n = i >> 3, c8 = i & 7;
        *(uint4*)(Bs + n * RSTRIDE + c8 * 8) = Wh4[i];
    }
    const float* A = Asrc ? Asrc : g_h1;

    for (int tile = blockIdx.x; tile < NT_N; tile += gridDim.x) {
        __syncthreads();
        for (int i = tid; i < 2048; i += 256) {
            int r = i >> 4, c4 = i & 15;
            int node = tile * 128 + r;
            float4 v = make_float4(0.f, 0.f, 0.f, 0.f);
            if (node < cN) v = ((const float4*)(A + (size_t)node * 64))[c4];
            __half2 h0 = __floats2half2_rn(v.x, v.y);
            __half2 h1 = __floats2half2_rn(v.z, v.w);
            *(__half2*)(As + r * RSTRIDE + c4 * 4)     = h0;
            *(__half2*)(As + r * RSTRIDE + c4 * 4 + 2) = h1;
        }
        __syncthreads();

#pragma unroll 1
        for (int p = 0; p < 2; p++) {
            float acc[16][4];
#pragma unroll
            for (int j = 0; j < 16; j++) {
                acc[j][0] = 0.f; acc[j][1] = 0.f; acc[j][2] = 0.f; acc[j][3] = 0.f;
            }
#pragma unroll
            for (int kk = 0; kk < 4; kk++) {
                const __half* ap  = As + (w * 16 + g) * RSTRIDE + kk * 16 + 2 * t;
                const __half* ap8 = ap + 8 * RSTRIDE;
                uint32_t a0 = *(const uint32_t*)ap;
                uint32_t a1 = *(const uint32_t*)ap8;
                uint32_t a2 = *(const uint32_t*)(ap + 8);
                uint32_t a3 = *(const uint32_t*)(ap8 + 8);
#pragma unroll
                for (int j = 0; j < 16; j++) {
                    const __half* bp = Bs + (p * 128 + j * 8 + g) * RSTRIDE + kk * 16 + 2 * t;
                    uint32_t b0 = *(const uint32_t*)bp;
                    uint32_t b1 = *(const uint32_t*)(bp + 8);
                    mma_f16(acc[j], a0, a1, a2, a3, b0, b1);
                }
            }
#pragma unroll
            for (int half = 0; half < 2; half++) {
                int r = w * 16 + g + half * 8;
                int node = tile * 128 + r;
                if (node < cN) {
                    __half* op = g_HH + (size_t)node * 768 + sec;
#pragma unroll
                    for (int j = 0; j < 16; j++)
                        *(__half2*)(op + p * 128 + j * 8 + 2 * t) =
                            __floats2half2_rn(acc[j][half * 2], acc[j][half * 2 + 1]);
                }
            }
        }
    }
}

// ---------------- fused edge kernel (fp16 MMA + fp16 gathers) ----------------
__global__ void __launch_bounds__(256, 2)
edge_mma_k(const float* __restrict__ Aew, const float* __restrict__ attn,
           const float* __restrict__ bias, int layer, int widx) {
    extern __shared__ __align__(16) unsigned char smraw[];
    __half* As = (__half*)smraw;                    // 128*72 halfs
    __half* Bs = As + 128 * RSTRIDE;                // 256*72 halfs
    float* bias_s = (float*)(smraw + 384 * RSTRIDE * 2);   // 256 floats
    float* attn_s = bias_s + 256;                          // 256 floats
    int tid = threadIdx.x, w = tid >> 5, lane = tid & 31;
    int g = lane >> 2, t = lane & 3;

    const uint4* Wh4 = (const uint4*)(g_Wh + widx * 16384);
    for (int i = tid; i < 2048; i += 256) {
        int n = i >> 3, c8 = i & 7;
        *(uint4*)(Bs + n * RSTRIDE + c8 * 8) = Wh4[i];
    }
    bias_s[tid] = bias[tid];
    attn_s[tid] = attn[tid];

    for (int tile = blockIdx.x; tile < NT_E; tile += gridDim.x) {
        __syncthreads();
        for (int i = tid; i < 2048; i += 256) {
            int r = i >> 4, c4 = i & 15;
            int pos = tile * 128 + r;
            if (layer == 0) {
                float4 v = ((const float4*)(Aew + (size_t)g_csr[pos] * 64))[c4];
                *(__half2*)(As + r * RSTRIDE + c4 * 4)     = __floats2half2_rn(v.x, v.y);
                *(__half2*)(As + r * RSTRIDE + c4 * 4 + 2) = __floats2half2_rn(v.z, v.w);
            } else {
                uint2 u = ((const uint2*)(g_w1 + (size_t)pos * 64))[c4];
                *(uint2*)(As + r * RSTRIDE + c4 * 4) = u;
            }
        }
        __syncthreads();

        float stg[32];
#pragma unroll 1
        for (int p = 0; p < 2; p++) {
            float acc[16][4];
#pragma unroll
            for (int j = 0; j < 16; j++) {
                acc[j][0] = 0.f; acc[j][1] = 0.f; acc[j][2] = 0.f; acc[j][3] = 0.f;
            }
#pragma unroll
            for (int kk = 0; kk < 4; kk++) {
                const __half* ap  = As + (w * 16 + g) * RSTRIDE + kk * 16 + 2 * t;
                const __half* ap8 = ap + 8 * RSTRIDE;
                uint32_t a0 = *(const uint32_t*)ap;
                uint32_t a1 = *(const uint32_t*)ap8;
                uint32_t a2 = *(const uint32_t*)(ap + 8);
                uint32_t a3 = *(const uint32_t*)(ap8 + 8);
#pragma unroll
                for (int j = 0; j < 16; j++) {
                    const __half* bp = Bs + (p * 128 + j * 8 + g) * RSTRIDE + kk * 16 + 2 * t;
                    uint32_t b0 = *(const uint32_t*)bp;
                    uint32_t b1 = *(const uint32_t*)(bp + 8);
                    mma_f16(acc[j], a0, a1, a2, a3, b0, b1);
                }
            }
            // epilogue: heads 2p (cols p*128+[0,64)) and 2p+1 (cols p*128+[64,128))
#pragma unroll
            for (int half = 0; half < 2; half++) {
                int r = w * 16 + g + half * 8;
                int pos = tile * 128 + r;
                int se = g_srcp[pos], de = g_dstp[pos];
                const __half* nip = g_HH + (size_t)se * 768;
                const __half* njp = g_HH + (size_t)de * 768 + 256;
                float aacc0 = 0.f, aacc1 = 0.f;
#pragma unroll
                for (int j = 0; j < 8; j++) {
                    int c0 = p * 128 + j * 8 + 2 * t;   // head 2p
                    int c1 = c0 + 64;                   // head 2p+1
                    float2 u0 = __half22float2(*(const __half2*)(nip + c0));
                    float2 v0 = __half22float2(*(const __half2*)(njp + c0));
                    float2 bi0 = *(const float2*)(bias_s + c0);
                    float2 at0 = *(const float2*)(attn_s + c0);
                    float f00 = acc[j][half * 2]     + u0.x + v0.x + bi0.x;
                    float f01 = acc[j][half * 2 + 1] + u0.y + v0.y + bi0.y;
                    f00 = f00 > 0.f ? f00 : LSLOPE * f00;
                    f01 = f01 > 0.f ? f01 : LSLOPE * f01;
                    aacc0 += at0.x * f00 + at0.y * f01;
                    float2 u1 = __half22float2(*(const __half2*)(nip + c1));
                    float2 v1 = __half22float2(*(const __half2*)(njp + c1));
                    float2 bi1 = *(const float2*)(bias_s + c1);
                    float2 at1 = *(const float2*)(attn_s + c1);
                    float f10 = acc[j + 8][half * 2]     + u1.x + v1.x + bi1.x;
                    float f11 = acc[j + 8][half * 2 + 1] + u1.y + v1.y + bi1.y;
                    f10 = f10 > 0.f ? f10 : LSLOPE * f10;
                    f11 = f11 > 0.f ? f11 : LSLOPE * f11;
                    aacc1 += at1.x * f10 + at1.y * f11;
                    if (layer == 0) {
                        int sidx = (half * 8 + j) * 2;
                        float s0 = f00 + f10, s1 = f01 + f11;
                        if (p == 0) { stg[sidx] = s0; stg[sidx + 1] = s1; }
                        else {
                            *(__half2*)(g_w1 + (size_t)pos * 64 + j * 8 + 2 * t) =
                                __floats2half2_rn((stg[sidx] + s0) * 0.25f,
                                                  (stg[sidx + 1] + s1) * 0.25f);
                        }
                    }
                }
                aacc0 += __shfl_xor_sync(0xffffffffu, aacc0, 1);
                aacc0 += __shfl_xor_sync(0xffffffffu, aacc0, 2);
                aacc1 += __shfl_xor_sync(0xffffffffu, aacc1, 1);
                aacc1 += __shfl_xor_sync(0xffffffffu, aacc1, 2);
                if (t == 0) {
                    g_a[(size_t)pos * 4 + 2 * p]     = aacc0;
                    g_a[(size_t)pos * 4 + 2 * p + 1] = aacc1;
                }
            }
        }
    }
}

// ---------------- softmax + aggregation (warp per dst node, fp16 gathers) ----------
__global__ void __launch_bounds__(256) agg_k(int layer) {
    int lane = threadIdx.x & 31, warp = threadIdx.x >> 5;
    int node = blockIdx.x * 8 + warp;
    float* hout = layer ? g_h2 : g_h1;
    float4* out4 = (float4*)(hout + (size_t)node * 64);
    int base = g_rowptr[node];
    int deg = g_rowptr[node + 1] - base;
    if (deg == 0) {
        if (lane < 16) out4[lane] = make_float4(0.f, 0.f, 0.f, 0.f);
        return;
    }
    const float4* a4 = (const float4*)g_a;
    float4 m = make_float4(-3.0e38f, -3.0e38f, -3.0e38f, -3.0e38f);
    for (int j = lane; j < deg; j += 32) m = max4(m, a4[base + j]);
#pragma unroll
    for (int off = 16; off >= 1; off >>= 1) m = max4(m, shflxor4(m, off));
    float4 ss = make_float4(0.f, 0.f, 0.f, 0.f);
    for (int j = lane; j < deg; j += 32) ss = add4(ss, exp4(sub4(a4[base + j], m)));
#pragma unroll
    for (int off = 16; off >= 1; off >>= 1) ss = add4(ss, shflxor4(ss, off));
    float4 inv = make_float4(1.f / ss.x, 1.f / ss.y, 1.f / ss.z, 1.f / ss.w);

    float4 accA = make_float4(0.f, 0.f, 0.f, 0.f);
    float4 accB = make_float4(0.f, 0.f, 0.f, 0.f);
    for (int j = 0; j < deg; j++) {
        int s = g_srcp[base + j];
        float4 av = a4[base + j];
        float4 wv = exp4(sub4(av, m));
        wv.x *= inv.x; wv.y *= inv.y; wv.z *= inv.z; wv.w *= inv.w;
        float wA = (lane < 16) ? wv.x : wv.y;
        float wB = (lane < 16) ? wv.z : wv.w;
        const __half* hn = g_HH + (size_t)s * 768 + 512;  // 'n' section
        uint2 ua = *(const uint2*)(hn + 4 * lane);
        uint2 ub = *(const uint2*)(hn + 128 + 4 * lane);
        float2 a0 = __half22float2(*(__half2*)&ua.x);
        float2 a1 = __half22float2(*(__half2*)&ua.y);
        float2 b0 = __half22float2(*(__half2*)&ub.x);
        float2 b1 = __half22float2(*(__half2*)&ub.y);
        accA.x = fmaf(wA, a0.x, accA.x); accA.y = fmaf(wA, a0.y, accA.y);
        accA.z = fmaf(wA, a1.x, accA.z); accA.w = fmaf(wA, a1.y, accA.w);
        accB.x = fmaf(wB, b0.x, accB.x); accB.y = fmaf(wB, b0.y, accB.y);
        accB.z = fmaf(wB, b1.x, accB.z); accB.w = fmaf(wB, b1.y, accB.w);
    }
    float4 t4 = add4(accA, accB);
    t4.x += __shfl_down_sync(0xffffffffu, t4.x, 16);
    t4.y += __shfl_down_sync(0xffffffffu, t4.y, 16);
    t4.z += __shfl_down_sync(0xffffffffu, t4.z, 16);
    t4.w += __shfl_down_sync(0xffffffffu, t4.w, 16);
    if (lane < 16)
        out4[lane] = make_float4(t4.x * 0.25f, t4.y * 0.25f, t4.z * 0.25f, t4.w * 0.25f);
}

// ---------------- pooling + classifier ----------------
__global__ void pool_k(const float* __restrict__ feat) {
    int g = blockIdx.x >> 5, sub = blockIdx.x & 31;
    int n0 = sub * 196;
    int n1 = n0 + 196; if (n1 > cNPG) n1 = cNPG;
    int t = threadIdx.x;  // 0..191
    float sum = 0.f;
    for (int n = n0; n < n1; n++) {
        int gn = g * cNPG + n;
        float v;
        if (t < 64)       v = feat[(size_t)gn * 64 + t];
        else if (t < 128) v = g_h1[(size_t)gn * 64 + (t - 64)];
        else              v = g_h2[(size_t)gn * 64 + (t - 128)];
        sum += v;
    }
    atomicAdd(&g_pooled[g * 192 + t], sum);
}
__global__ void final_k(const float* __restrict__ Wlin, const float* __restrict__ blin,
                        float* __restrict__ out) {
    int t = threadIdx.x;
    if (t < 16) {
        int b = t >> 1, c = t & 1;
        float acc = blin[c];
        const float invn = 1.0f / (float)cNPG;
        for (int k = 0; k < 192; k++)
            acc += (g_pooled[b * 192 + k] * invn) * Wlin[k * 2 + c];
        out[t] = acc;
    }
}

// ---------------- launch ----------------
extern "C" void kernel_launch(void* const* d_in, const int* in_sizes, int n_in,
                              void* d_out, int out_size) {
    const float* feat   = (const float*)d_in[0];
    const float* ew     = (const float*)d_in[1];
    const int*   src    = (const int*)d_in[2];
    const int*   dst    = (const int*)d_in[3];
    const float* W_node = (const float*)d_in[4];
    const float* W_ni   = (const float*)d_in[5];
    const float* W_nj   = (const float*)d_in[6];
    const float* W_fij  = (const float*)d_in[7];
    const float* attn   = (const float*)d_in[8];
    const float* bias_e = (const float*)d_in[9];
    const float* W_lin  = (const float*)d_in[10];
    const float* b_lin  = (const float*)d_in[11];
    float* out = (float*)d_out;

    const int NSMEM = 384 * RSTRIDE * 2;          // 55296 B
    const int ESMEM = 384 * RSTRIDE * 2 + 2048;   // 57344 B
    cudaFuncSetAttribute((const void*)node_mma_k,
                         cudaFuncAttributeMaxDynamicSharedMemorySize, NSMEM);
    cudaFuncSetAttribute((const void*)edge_mma_k,
                         cudaFuncAttributeMaxDynamicSharedMemorySize, ESMEM);

    // CSR build + weight prep
    zero_k<<<(cN + 255) / 256, 256>>>();
    hist_k<<<(cE + 255) / 256, 256>>>(dst);
    scan1_k<<<98, 512>>>();
    scan2_k<<<1, 32>>>();
    scan3_k<<<(cN + 255) / 256, 256>>>();
    scat_k<<<(cE + 255) / 256, 256>>>(src, dst);
    prep_k<<<512, 256>>>(W_fij, W_ni, W_nj, W_node);

    // ---- layer 0 ----
    node_mma_k<<<PGRID, 256, NSMEM>>>(feat, 2, 0);     // ni0
    node_mma_k<<<PGRID, 256, NSMEM>>>(feat, 4, 256);   // nj0
    node_mma_k<<<PGRID, 256, NSMEM>>>(feat, 6, 512);   // node0
    edge_mma_k<<<PGRID, 256, ESMEM>>>(ew, attn, bias_e, 0, 0);
    agg_k<<<cN / 8, 256>>>(0);

    // ---- layer 1 ----
    node_mma_k<<<PGRID, 256, NSMEM>>>(nullptr, 3, 0);   // ni1
    node_mma_k<<<PGRID, 256, NSMEM>>>(nullptr, 5, 256); // nj1
    node_mma_k<<<PGRID, 256, NSMEM>>>(nullptr, 7, 512); // node1
    edge_mma_k<<<PGRID, 256, ESMEM>>>(ew, attn + 256, bias_e + 256, 1, 1);
    agg_k<<<cN / 8, 256>>>(1);

    // ---- JK pooling + classifier ----
    pool_k<<<cB * 32, 192>>>(feat);
    final_k<<<1, 32>>>(W_lin, b_lin, out);
}